// round 3
// baseline (speedup 1.0000x reference)
#include <cuda_runtime.h>
#include <math.h>
#include <stdint.h>

// Problem constants
#define BB 4
#define LL 2052
#define CC 1024
#define HH 16
#define DD 64
#define NREG 4
#define MROWS (BB*LL)          // 8208
#define QKVN (3*CC)            // 3072

// Scratch (device globals: allocation-free)
__device__ float g_qkv[(size_t)MROWS * QKVN];   // ~100.9 MB
__device__ float g_att[(size_t)MROWS * CC];     // ~33.6 MB

__device__ __forceinline__ float ex2f(float x) {
    float y; asm("ex2.approx.f32 %0, %1;" : "=f"(y) : "f"(x)); return y;
}

// ---------------------------------------------------------------------------
// SGEMM: C[M,N] = A[M,K] @ B[K,N] + bias[N].  BM=BN=128, BK=8, 256 threads,
// 8x8 per-thread microtile, float4 loads. Only M can be non-multiple of 128.
// ---------------------------------------------------------------------------
__global__ __launch_bounds__(256) void sgemm_bias_kernel(
    const float* __restrict__ A, const float* __restrict__ Bm,
    const float* __restrict__ bias, float* __restrict__ Cm,
    int M, int N, int K)
{
    __shared__ float As[8][128];
    __shared__ float Bs[8][128];

    const int tid = threadIdx.x;
    const int bx  = blockIdx.x;   // N tile
    const int by  = blockIdx.y;   // M tile
    const int row0 = by * 128;
    const int col0 = bx * 128;

    const int tx = tid & 15;      // 0..15 -> n
    const int ty = tid >> 4;      // 0..15 -> m

    const int aRow = tid >> 1;          // 0..127
    const int aCol = (tid & 1) * 4;     // 0 or 4
    const int bRow = tid >> 5;          // 0..7
    const int bCol = (tid & 31) * 4;    // 0..124

    const bool aValid = (row0 + aRow) < M;
    const float* Aptr = A + (size_t)(row0 + aRow) * K + aCol;
    const float* Bptr = Bm + (size_t)bRow * N + col0 + bCol;

    float acc[8][8];
    #pragma unroll
    for (int i = 0; i < 8; i++)
        #pragma unroll
        for (int j = 0; j < 8; j++) acc[i][j] = 0.f;

    for (int k0 = 0; k0 < K; k0 += 8) {
        float4 av = make_float4(0.f, 0.f, 0.f, 0.f);
        if (aValid) av = *(const float4*)(Aptr + k0);
        As[aCol + 0][aRow] = av.x;
        As[aCol + 1][aRow] = av.y;
        As[aCol + 2][aRow] = av.z;
        As[aCol + 3][aRow] = av.w;

        float4 bv = *(const float4*)(Bptr + (size_t)k0 * N);
        *(float4*)&Bs[bRow][bCol] = bv;
        __syncthreads();

        #pragma unroll
        for (int k = 0; k < 8; ++k) {
            float ar[8], br[8];
            *(float4*)(ar)     = *(const float4*)&As[k][ty * 8];
            *(float4*)(ar + 4) = *(const float4*)&As[k][ty * 8 + 4];
            *(float4*)(br)     = *(const float4*)&Bs[k][tx * 8];
            *(float4*)(br + 4) = *(const float4*)&Bs[k][tx * 8 + 4];
            #pragma unroll
            for (int i = 0; i < 8; i++)
                #pragma unroll
                for (int j = 0; j < 8; j++)
                    acc[i][j] = fmaf(ar[i], br[j], acc[i][j]);
        }
        __syncthreads();
    }

    const int cbase = col0 + tx * 8;
    float bb[8];
    #pragma unroll
    for (int j = 0; j < 8; j++) bb[j] = bias[cbase + j];

    #pragma unroll
    for (int i = 0; i < 8; i++) {
        int r = row0 + ty * 8 + i;
        if (r < M) {
            float4 v0 = make_float4(acc[i][0] + bb[0], acc[i][1] + bb[1],
                                    acc[i][2] + bb[2], acc[i][3] + bb[3]);
            float4 v1 = make_float4(acc[i][4] + bb[4], acc[i][5] + bb[5],
                                    acc[i][6] + bb[6], acc[i][7] + bb[7]);
            *(float4*)&Cm[(size_t)r * N + cbase]     = v0;
            *(float4*)&Cm[(size_t)r * N + cbase + 4] = v1;
        }
    }
}

// ---------------------------------------------------------------------------
// RoPE in-place on q (s=0) and k (s=1) for l >= NREG.
// One thread handles one (d, d+32) rotation pair.
// ---------------------------------------------------------------------------
#define ROPE_TOTAL (BB * (LL - NREG) * 2 * HH * (DD/2))   // 8,388,608

__global__ __launch_bounds__(256) void rope_kernel(
    float* __restrict__ qkv, const float* __restrict__ rope)
{
    int gid = blockIdx.x * 256 + threadIdx.x;
    if (gid >= ROPE_TOTAL) return;
    int dp = gid & 31;  int r = gid >> 5;
    int h  = r & 15;    r >>= 4;
    int s  = r & 1;     r >>= 1;
    int l4 = r & 2047;  int b = r >> 11;
    int l  = l4 + NREG;

    float* p = qkv + ((size_t)(b * LL + l) * 3 + s) * CC + h * DD;
    const float* cs = rope + (size_t)l4 * DD;
    const float* sn = rope + (size_t)(LL - NREG) * DD + (size_t)l4 * DD;

    float x1 = p[dp], x2 = p[dp + 32];
    p[dp]      = x1 * cs[dp]      - x2 * sn[dp];
    p[dp + 32] = x2 * cs[dp + 32] + x1 * sn[dp + 32];
}

// ---------------------------------------------------------------------------
// Flash attention fp32. Block = (q_tile, h, b), 256 threads, 64x64 tiles.
// Softmax in base-2 (scale*log2e folded into Q); raw ex2.approx.
// Output layout: g_att[(b*L + l)*C + h*D + d]  (== transpose(0,2,1,3).reshape)
// ---------------------------------------------------------------------------
#define SSTR 65
#define ATTN_SMEM (4 * 64 * SSTR * (int)sizeof(float))   // 66560 B

__global__ __launch_bounds__(256) void attn_kernel(
    const float* __restrict__ qkv, float* __restrict__ out)
{
    extern __shared__ float sm[];
    float* Qs = sm;
    float* Ks = Qs + 64 * SSTR;
    float* Vs = Ks + 64 * SSTR;
    float* Ps = Vs + 64 * SSTR;

    const int qt = blockIdx.x, h = blockIdx.y, b = blockIdx.z;
    const int tid = threadIdx.x;
    const int tx = tid & 15, ty = tid >> 4;

    const size_t rstr = QKVN;  // 3072 floats between consecutive l
    const float* qbase = qkv + (size_t)b * LL * rstr + h * DD;
    const float* kbase = qbase + CC;
    const float* vbase = qbase + 2 * CC;
    const float qscale = 0.125f * 1.4426950408889634f;  // 1/sqrt(D) * log2(e)

    // Load Q tile (scaled)
    for (int idx = tid; idx < 64 * 64; idx += 256) {
        int r = idx >> 6, d = idx & 63;
        int l = qt * 64 + r;
        Qs[r * SSTR + d] = (l < LL) ? qbase[(size_t)l * rstr + d] * qscale : 0.f;
    }

    float m[4], lsum[4], o[4][4];
    #pragma unroll
    for (int i = 0; i < 4; i++) {
        m[i] = -1e30f; lsum[i] = 0.f;
        #pragma unroll
        for (int c = 0; c < 4; c++) o[i][c] = 0.f;
    }

    const int nkt = (LL + 63) / 64;   // 33
    for (int kt = 0; kt < nkt; ++kt) {
        __syncthreads();   // protect Ks/Vs/Ps from prior iteration readers
        for (int idx = tid; idx < 64 * 64; idx += 256) {
            int r = idx >> 6, d = idx & 63;
            int lkv = kt * 64 + r;
            float kvv = 0.f, vvv = 0.f;
            if (lkv < LL) {
                kvv = kbase[(size_t)lkv * rstr + d];
                vvv = vbase[(size_t)lkv * rstr + d];
            }
            Ks[r * SSTR + d] = kvv;
            Vs[r * SSTR + d] = vvv;
        }
        __syncthreads();

        // S = Q @ K^T (base-2 logits)
        float s[4][4];
        #pragma unroll
        for (int i = 0; i < 4; i++)
            #pragma unroll
            for (int j = 0; j < 4; j++) s[i][j] = 0.f;

        #pragma unroll 4
        for (int d = 0; d < 64; ++d) {
            float qv[4], kv[4];
            #pragma unroll
            for (int i = 0; i < 4; i++) qv[i] = Qs[(ty * 4 + i) * SSTR + d];
            #pragma unroll
            for (int j = 0; j < 4; j++) kv[j] = Ks[(tx * 4 + j) * SSTR + d];
            #pragma unroll
            for (int i = 0; i < 4; i++)
                #pragma unroll
                for (int j = 0; j < 4; j++)
                    s[i][j] = fmaf(qv[i], kv[j], s[i][j]);
        }

        // mask invalid kv columns (tail tile)
        int kv0 = kt * 64 + tx * 4;
        if (kv0 + 3 >= LL) {
            #pragma unroll
            for (int j = 0; j < 4; j++)
                if (kv0 + j >= LL)
                    #pragma unroll
                    for (int i = 0; i < 4; i++) s[i][j] = -1e30f;
        }

        // online softmax (per q-row, reduced across the 16 tx lanes)
        #pragma unroll
        for (int i = 0; i < 4; i++) {
            float tmax = fmaxf(fmaxf(s[i][0], s[i][1]), fmaxf(s[i][2], s[i][3]));
            #pragma unroll
            for (int ofs = 1; ofs < 16; ofs <<= 1)
                tmax = fmaxf(tmax, __shfl_xor_sync(0xffffffffu, tmax, ofs));
            float mnew = fmaxf(m[i], tmax);
            float corr = ex2f(m[i] - mnew);
            m[i] = mnew;
            float rs = 0.f;
            #pragma unroll
            for (int j = 0; j < 4; j++) {
                s[i][j] = ex2f(s[i][j] - mnew);
                rs += s[i][j];
            }
            #pragma unroll
            for (int ofs = 1; ofs < 16; ofs <<= 1)
                rs += __shfl_xor_sync(0xffffffffu, rs, ofs);
            lsum[i] = lsum[i] * corr + rs;
            #pragma unroll
            for (int c = 0; c < 4; c++) o[i][c] *= corr;
            #pragma unroll
            for (int j = 0; j < 4; j++)
                Ps[(ty * 4 + i) * SSTR + tx * 4 + j] = s[i][j];
        }
        __syncthreads();

        // O += P @ V
        #pragma unroll 4
        for (int j = 0; j < 64; ++j) {
            float pv[4], vv[4];
            #pragma unroll
            for (int i = 0; i < 4; i++) pv[i] = Ps[(ty * 4 + i) * SSTR + j];
            #pragma unroll
            for (int c = 0; c < 4; c++) vv[c] = Vs[j * SSTR + tx * 4 + c];
            #pragma unroll
            for (int i = 0; i < 4; i++)
                #pragma unroll
                for (int c = 0; c < 4; c++)
                    o[i][c] = fmaf(pv[i], vv[c], o[i][c]);
        }
    }

    #pragma unroll
    for (int i = 0; i < 4; i++) {
        int l = qt * 64 + ty * 4 + i;
        if (l < LL) {
            float inv = 1.f / lsum[i];
            size_t base = ((size_t)(b * LL + l)) * CC + h * DD + tx * 4;
            #pragma unroll
            for (int c = 0; c < 4; c++) out[base + c] = o[i][c] * inv;
        }
    }
}

// ---------------------------------------------------------------------------
// LayerNorm in-place, one block per row of 1024.
// ---------------------------------------------------------------------------
__global__ __launch_bounds__(256) void ln_kernel(
    float* __restrict__ x, const float* __restrict__ gamma,
    const float* __restrict__ beta)
{
    const int row = blockIdx.x;
    float* p = x + (size_t)row * CC;
    const int tid = threadIdx.x;

    float v[4], sum = 0.f, sq = 0.f;
    #pragma unroll
    for (int j = 0; j < 4; j++) {
        v[j] = p[tid + j * 256];
        sum += v[j];
        sq  = fmaf(v[j], v[j], sq);
    }
    #pragma unroll
    for (int o = 16; o; o >>= 1) {
        sum += __shfl_xor_sync(0xffffffffu, sum, o);
        sq  += __shfl_xor_sync(0xffffffffu, sq, o);
    }
    __shared__ float rs[8], rq[8];
    int wid = tid >> 5, lane = tid & 31;
    if (lane == 0) { rs[wid] = sum; rq[wid] = sq; }
    __syncthreads();
    if (tid == 0) {
        float a = 0.f, b2 = 0.f;
        #pragma unroll
        for (int i = 0; i < 8; i++) { a += rs[i]; b2 += rq[i]; }
        rs[0] = a; rq[0] = b2;
    }
    __syncthreads();
    sum = rs[0]; sq = rq[0];

    float mu   = sum * (1.f / CC);
    float var  = sq * (1.f / CC) - mu * mu;
    float rstd = rsqrtf(var + 1e-5f);
    #pragma unroll
    for (int j = 0; j < 4; j++) {
        int c = tid + j * 256;
        p[c] = (v[j] - mu) * rstd * gamma[c] + beta[c];
    }
}

// ---------------------------------------------------------------------------
extern "C" void kernel_launch(void* const* d_in, const int* in_sizes, int n_in,
                              void* d_out, int out_size)
{
    const float* x     = (const float*)d_in[0];
    const float* rope  = (const float*)d_in[1];
    const float* Wqkv  = (const float*)d_in[2];
    const float* bqkv  = (const float*)d_in[3];
    const float* Wproj = (const float*)d_in[4];
    const float* bproj = (const float*)d_in[5];
    const float* gamma = (const float*)d_in[6];
    const float* beta  = (const float*)d_in[7];
    float* out = (float*)d_out;

    float *qkv = nullptr, *att = nullptr;
    cudaGetSymbolAddress((void**)&qkv, g_qkv);
    cudaGetSymbolAddress((void**)&att, g_att);

    // 1. QKV GEMM + bias: [8208,1024] @ [1024,3072]
    {
        dim3 grid(QKVN / 128, (MROWS + 127) / 128);
        sgemm_bias_kernel<<<grid, 256>>>(x, Wqkv, bqkv, qkv, MROWS, QKVN, CC);
    }
    // 2. RoPE in-place on q,k
    {
        int blocks = (ROPE_TOTAL + 255) / 256;
        rope_kernel<<<blocks, 256>>>(qkv, rope);
    }
    // 3. Flash attention -> g_att in [B,L,C] layout
    {
        cudaFuncSetAttribute(attn_kernel,
                             cudaFuncAttributeMaxDynamicSharedMemorySize,
                             ATTN_SMEM);
        dim3 grid((LL + 63) / 64, HH, BB);
        attn_kernel<<<grid, 256, ATTN_SMEM>>>(qkv, att);
    }
    // 4. LayerNorm in-place
    ln_kernel<<<MROWS, 256>>>(att, gamma, beta);

    // 5. Proj GEMM + bias: [8208,1024] @ [1024,1024] -> out
    {
        dim3 grid(CC / 128, (MROWS + 127) / 128);
        sgemm_bias_kernel<<<grid, 256>>>(att, Wproj, bproj, out, MROWS, CC, CC);
    }
}

// round 5
// speedup vs baseline: 1.9303x; 1.9303x over previous
#include <cuda_runtime.h>
#include <cuda_fp16.h>
#include <math.h>
#include <stdint.h>

// Problem constants
#define BB 4
#define LL 2052
#define CC 1024
#define HH 16
#define DD 64
#define NREG 4
#define MROWS (BB*LL)          // 8208
#define QKVN (3*CC)            // 3072

// ---------------------------------------------------------------------------
// Device scratch
// ---------------------------------------------------------------------------
__device__ float  g_qkv[(size_t)MROWS * QKVN];     // fp32 qkv (rope applied here)
__device__ float  g_att[(size_t)MROWS * CC];       // fp32 attention output
__device__ __half g_xh[(size_t)MROWS * CC];
__device__ __half g_xl[(size_t)MROWS * CC];
__device__ __half g_qh[(size_t)MROWS * QKVN];
__device__ __half g_ql[(size_t)MROWS * QKVN];
__device__ __half g_ah[(size_t)MROWS * CC];
__device__ __half g_al[(size_t)MROWS * CC];
__device__ __half g_wh[(size_t)CC * QKVN];
__device__ __half g_wl[(size_t)CC * QKVN];
__device__ __half g_ph[(size_t)CC * CC];
__device__ __half g_pl[(size_t)CC * CC];

__device__ __forceinline__ float ex2f(float x) {
    float y; asm("ex2.approx.f32 %0, %1;" : "=f"(y) : "f"(x)); return y;
}

__device__ __forceinline__ uint32_t packh(__half lo, __half hi) {
    return ((uint32_t)__half_as_ushort(hi) << 16) | (uint32_t)__half_as_ushort(lo);
}

// mma.sync m16n8k16 row.col f32 += f16*f16
__device__ __forceinline__ void mma16816(float* d, const uint32_t* a, const uint32_t* b) {
    asm volatile(
        "mma.sync.aligned.m16n8k16.row.col.f32.f16.f16.f32 "
        "{%0,%1,%2,%3}, {%4,%5,%6,%7}, {%8,%9}, {%0,%1,%2,%3};\n"
        : "+f"(d[0]), "+f"(d[1]), "+f"(d[2]), "+f"(d[3])
        : "r"(a[0]), "r"(a[1]), "r"(a[2]), "r"(a[3]), "r"(b[0]), "r"(b[1]));
}

// ---------------------------------------------------------------------------
// Split fp32 -> (hi, lo) fp16.  n must be a multiple of 4.
// ---------------------------------------------------------------------------
__global__ __launch_bounds__(256) void split_kernel(
    const float* __restrict__ src, __half* __restrict__ hi,
    __half* __restrict__ lo, int n)
{
    int i = (blockIdx.x * 256 + threadIdx.x) * 4;
    if (i >= n) return;
    float4 v = *(const float4*)(src + i);
    __half h0 = __float2half_rn(v.x), h1 = __float2half_rn(v.y);
    __half h2 = __float2half_rn(v.z), h3 = __float2half_rn(v.w);
    __half l0 = __float2half_rn(v.x - __half2float(h0));
    __half l1 = __float2half_rn(v.y - __half2float(h1));
    __half l2 = __float2half_rn(v.z - __half2float(h2));
    __half l3 = __float2half_rn(v.w - __half2float(h3));
    *(uint2*)(hi + i) = make_uint2(packh(h0, h1), packh(h2, h3));
    *(uint2*)(lo + i) = make_uint2(packh(l0, l1), packh(l2, l3));
}

// ---------------------------------------------------------------------------
// Split-fp16 tensor-core GEMM: C[M,N] = (Ah+Al)(Bh+Bl) + bias
// BM=128 BN=128 BK=32, 256 threads (8 warps, 2x4), warp tile 64x32.
// ---------------------------------------------------------------------------
#define ASTR 40   // smem k-stride in halves (80B, 16B aligned, conflict-free frags)

__global__ __launch_bounds__(256) void gemm_f16s(
    const __half* __restrict__ Ah, const __half* __restrict__ Al,
    const __half* __restrict__ Bh, const __half* __restrict__ Bl,
    const float* __restrict__ bias, float* __restrict__ C,
    int M, int N, int K)
{
    __shared__ __half As[2][128][ASTR];   // [hi/lo][row][k]
    __shared__ __half Bt[2][128][ASTR];   // [hi/lo][n][k]

    const int tid = threadIdx.x, lane = tid & 31, wid = tid >> 5;
    const int g = lane >> 2, tig = lane & 3;
    const int row0 = blockIdx.y * 128, col0 = blockIdx.x * 128;
    const int wm = (wid & 1) * 64, wn = (wid >> 1) * 32;

    float acc[4][4][4];
    #pragma unroll
    for (int mt = 0; mt < 4; mt++)
        #pragma unroll
        for (int nt = 0; nt < 4; nt++)
            #pragma unroll
            for (int r = 0; r < 4; r++) acc[mt][nt][r] = 0.f;

    const int arow = tid >> 1, aseg = (tid & 1) * 16;
    const int bk = (tid & 15) * 2, bn = (tid >> 4) * 8;
    const bool avalid = (row0 + arow) < M;
    const uint4 z4 = make_uint4(0, 0, 0, 0);

    for (int kt = 0; kt < K; kt += 32) {
        // --- stage A (row-major) ---
        {
            size_t go = (size_t)(row0 + arow) * K + kt + aseg;
            uint4 h0 = avalid ? *(const uint4*)(Ah + go)     : z4;
            uint4 h1 = avalid ? *(const uint4*)(Ah + go + 8) : z4;
            uint4 l0 = avalid ? *(const uint4*)(Al + go)     : z4;
            uint4 l1 = avalid ? *(const uint4*)(Al + go + 8) : z4;
            *(uint4*)&As[0][arow][aseg]     = h0;
            *(uint4*)&As[0][arow][aseg + 8] = h1;
            *(uint4*)&As[1][arow][aseg]     = l0;
            *(uint4*)&As[1][arow][aseg + 8] = l1;
        }
        // --- stage B transposed: Bt[n][k] ---
        #pragma unroll
        for (int hl = 0; hl < 2; hl++) {
            const __half* Bp = hl ? Bl : Bh;
            size_t go = (size_t)(kt + bk) * N + col0 + bn;
            uint4 r0 = *(const uint4*)(Bp + go);
            uint4 r1 = *(const uint4*)(Bp + go + N);
            const __half* p0 = (const __half*)&r0;
            const __half* p1 = (const __half*)&r1;
            #pragma unroll
            for (int j = 0; j < 8; j++)
                *(uint32_t*)&Bt[hl][bn + j][bk] = packh(p0[j], p1[j]);
        }
        __syncthreads();

        #pragma unroll
        for (int ks = 0; ks < 2; ks++) {
            const int c = ks * 16 + 2 * tig;
            uint32_t afh[4][4], afl[4][4], bfh[4][2], bfl[4][2];
            #pragma unroll
            for (int mt = 0; mt < 4; mt++) {
                int r = wm + mt * 16 + g;
                afh[mt][0] = *(const uint32_t*)&As[0][r][c];
                afh[mt][1] = *(const uint32_t*)&As[0][r + 8][c];
                afh[mt][2] = *(const uint32_t*)&As[0][r][c + 8];
                afh[mt][3] = *(const uint32_t*)&As[0][r + 8][c + 8];
                afl[mt][0] = *(const uint32_t*)&As[1][r][c];
                afl[mt][1] = *(const uint32_t*)&As[1][r + 8][c];
                afl[mt][2] = *(const uint32_t*)&As[1][r][c + 8];
                afl[mt][3] = *(const uint32_t*)&As[1][r + 8][c + 8];
            }
            #pragma unroll
            for (int nt = 0; nt < 4; nt++) {
                int n = wn + nt * 8 + g;
                bfh[nt][0] = *(const uint32_t*)&Bt[0][n][c];
                bfh[nt][1] = *(const uint32_t*)&Bt[0][n][c + 8];
                bfl[nt][0] = *(const uint32_t*)&Bt[1][n][c];
                bfl[nt][1] = *(const uint32_t*)&Bt[1][n][c + 8];
            }
            #pragma unroll
            for (int mt = 0; mt < 4; mt++)
                #pragma unroll
                for (int nt = 0; nt < 4; nt++) {
                    mma16816(acc[mt][nt], afh[mt], bfh[nt]);
                    mma16816(acc[mt][nt], afh[mt], bfl[nt]);
                    mma16816(acc[mt][nt], afl[mt], bfh[nt]);
                }
        }
        __syncthreads();
    }

    // epilogue
    #pragma unroll
    for (int mt = 0; mt < 4; mt++) {
        int ra = row0 + wm + mt * 16 + g;
        int rb = ra + 8;
        #pragma unroll
        for (int nt = 0; nt < 4; nt++) {
            int cc = col0 + wn + nt * 8 + 2 * tig;
            float b0 = bias[cc], b1 = bias[cc + 1];
            if (ra < M)
                *(float2*)&C[(size_t)ra * N + cc] =
                    make_float2(acc[mt][nt][0] + b0, acc[mt][nt][1] + b1);
            if (rb < M)
                *(float2*)&C[(size_t)rb * N + cc] =
                    make_float2(acc[mt][nt][2] + b0, acc[mt][nt][3] + b1);
        }
    }
}

// ---------------------------------------------------------------------------
// RoPE in-place on fp32 qkv (q: s=0, k: s=1) for l >= NREG.
// ---------------------------------------------------------------------------
#define ROPE_TOTAL (BB * (LL - NREG) * 2 * HH * (DD/2))

__global__ __launch_bounds__(256) void rope_kernel(
    float* __restrict__ qkv, const float* __restrict__ rope)
{
    int gid = blockIdx.x * 256 + threadIdx.x;
    if (gid >= ROPE_TOTAL) return;
    int dp = gid & 31;  int r = gid >> 5;
    int h  = r & 15;    r >>= 4;
    int s  = r & 1;     r >>= 1;
    int l4 = r & 2047;  int b = r >> 11;
    int l  = l4 + NREG;

    float* p = qkv + ((size_t)(b * LL + l) * 3 + s) * CC + h * DD;
    const float* cs = rope + (size_t)l4 * DD;
    const float* sn = rope + (size_t)(LL - NREG) * DD + (size_t)l4 * DD;

    float x1 = p[dp], x2 = p[dp + 32];
    p[dp]      = x1 * cs[dp]      - x2 * sn[dp];
    p[dp + 32] = x2 * cs[dp + 32] + x1 * sn[dp + 32];
}

// ---------------------------------------------------------------------------
// Tensor-core flash attention, split fp16.
// 128 threads (4 warps), Br=64 (16 q-rows/warp), Bc=64, D=64.
// Q frags register-resident; K untransposed; V transposed in smem.
// ---------------------------------------------------------------------------
#define KSTR 72   // smem stride in halves

__global__ __launch_bounds__(128) void attn_f16s(
    const __half* __restrict__ qh, const __half* __restrict__ ql,
    float* __restrict__ out)
{
    __shared__ __half Ks[2][64][KSTR];   // [hi/lo][kv][d]
    __shared__ __half Vt[2][64][KSTR];   // [hi/lo][d][kv]

    const int qt = blockIdx.x, h = blockIdx.y, b = blockIdx.z;
    const int tid = threadIdx.x, lane = tid & 31, wid = tid >> 5;
    const int g = lane >> 2, tig = lane & 3;
    const size_t rstr = QKVN;
    const __half* qbh = qh + (size_t)b * LL * rstr + h * DD;
    const __half* qbl = ql + (size_t)b * LL * rstr + h * DD;
    const __half* kbh = qbh + CC;
    const __half* kbl = qbl + CC;
    const __half* vbh = qbh + 2 * CC;
    const __half* vbl = qbl + 2 * CC;
    const uint4 z4 = make_uint4(0, 0, 0, 0);

    // ---- Q fragments (register resident) ----
    uint32_t qfh[4][4], qfl[4][4];
    const int q0 = qt * 64 + wid * 16;
    const int qra = q0 + g, qrb = qra + 8;
    const bool va = qra < LL, vb = qrb < LL;
    #pragma unroll
    for (int kt = 0; kt < 4; kt++) {
        int c = kt * 16 + 2 * tig;
        qfh[kt][0] = va ? *(const uint32_t*)(qbh + (size_t)qra * rstr + c) : 0u;
        qfh[kt][1] = vb ? *(const uint32_t*)(qbh + (size_t)qrb * rstr + c) : 0u;
        qfh[kt][2] = va ? *(const uint32_t*)(qbh + (size_t)qra * rstr + c + 8) : 0u;
        qfh[kt][3] = vb ? *(const uint32_t*)(qbh + (size_t)qrb * rstr + c + 8) : 0u;
        qfl[kt][0] = va ? *(const uint32_t*)(qbl + (size_t)qra * rstr + c) : 0u;
        qfl[kt][1] = vb ? *(const uint32_t*)(qbl + (size_t)qrb * rstr + c) : 0u;
        qfl[kt][2] = va ? *(const uint32_t*)(qbl + (size_t)qra * rstr + c + 8) : 0u;
        qfl[kt][3] = vb ? *(const uint32_t*)(qbl + (size_t)qrb * rstr + c + 8) : 0u;
    }

    float m_a = -1e30f, m_b = -1e30f, l_a = 0.f, l_b = 0.f;
    float o[8][4];
    #pragma unroll
    for (int dt = 0; dt < 8; dt++)
        #pragma unroll
        for (int r = 0; r < 4; r++) o[dt][r] = 0.f;

    const float sc = 0.125f * 1.4426950408889634f;   // 1/sqrt(D) * log2(e)
    const int nkt = (LL + 63) / 64;                  // 33

    for (int t = 0; t < nkt; ++t) {
        __syncthreads();   // previous tile fully consumed
        const int kvb = t * 64;
        // --- K tiles (direct copy, kv-major) ---
        {
            int r = tid >> 1, sg = (tid & 1) * 32;
            int lkv = kvb + r;
            bool v = lkv < LL;
            size_t go = (size_t)lkv * rstr + sg;
            #pragma unroll
            for (int i = 0; i < 4; i++) {
                *(uint4*)&Ks[0][r][sg + i * 8] = v ? *(const uint4*)(kbh + go + i * 8) : z4;
                *(uint4*)&Ks[1][r][sg + i * 8] = v ? *(const uint4*)(kbl + go + i * 8) : z4;
            }
        }
        // --- V tiles transposed: Vt[d][kv] ---
        #pragma unroll
        for (int it = 0; it < 2; it++) {
            int task = tid + it * 128;
            int kvp = (task & 31) * 2, dc = (task >> 5) * 8;
            int lkv = kvb + kvp;
            bool v0 = lkv < LL, v1 = (lkv + 1) < LL;
            #pragma unroll
            for (int hl = 0; hl < 2; hl++) {
                const __half* vsrc = hl ? vbl : vbh;
                uint4 r0 = v0 ? *(const uint4*)(vsrc + (size_t)lkv * rstr + dc) : z4;
                uint4 r1 = v1 ? *(const uint4*)(vsrc + (size_t)(lkv + 1) * rstr + dc) : z4;
                const __half* p0 = (const __half*)&r0;
                const __half* p1 = (const __half*)&r1;
                #pragma unroll
                for (int j = 0; j < 8; j++)
                    *(uint32_t*)&Vt[hl][dc + j][kvp] = packh(p0[j], p1[j]);
            }
        }
        __syncthreads();

        // --- S = Q @ K^T ---
        float s[8][4];
        #pragma unroll
        for (int nt = 0; nt < 8; nt++)
            #pragma unroll
            for (int r = 0; r < 4; r++) s[nt][r] = 0.f;

        #pragma unroll
        for (int nt = 0; nt < 8; nt++) {
            int kr = nt * 8 + g;
            #pragma unroll
            for (int kt = 0; kt < 4; kt++) {
                int c = kt * 16 + 2 * tig;
                uint32_t bh[2], bl[2];
                bh[0] = *(const uint32_t*)&Ks[0][kr][c];
                bh[1] = *(const uint32_t*)&Ks[0][kr][c + 8];
                bl[0] = *(const uint32_t*)&Ks[1][kr][c];
                bl[1] = *(const uint32_t*)&Ks[1][kr][c + 8];
                mma16816(s[nt], qfh[kt], bh);
                mma16816(s[nt], qfh[kt], bl);
                mma16816(s[nt], qfl[kt], bh);
            }
        }
        // scale to base-2 logits
        #pragma unroll
        for (int nt = 0; nt < 8; nt++)
            #pragma unroll
            for (int r = 0; r < 4; r++) s[nt][r] *= sc;

        // mask tail kv (only last tile)
        if (t == nkt - 1) {
            #pragma unroll
            for (int nt = 0; nt < 8; nt++) {
                int kv0 = kvb + nt * 8 + 2 * tig;
                if (kv0 >= LL)     { s[nt][0] = -1e30f; s[nt][2] = -1e30f; }
                if (kv0 + 1 >= LL) { s[nt][1] = -1e30f; s[nt][3] = -1e30f; }
            }
        }

        // --- online softmax (rows: a=g-row, b=g+8-row; quad-shuffles) ---
        float ma = -1e30f, mb = -1e30f;
        #pragma unroll
        for (int nt = 0; nt < 8; nt++) {
            ma = fmaxf(ma, fmaxf(s[nt][0], s[nt][1]));
            mb = fmaxf(mb, fmaxf(s[nt][2], s[nt][3]));
        }
        ma = fmaxf(ma, __shfl_xor_sync(0xffffffffu, ma, 1));
        ma = fmaxf(ma, __shfl_xor_sync(0xffffffffu, ma, 2));
        mb = fmaxf(mb, __shfl_xor_sync(0xffffffffu, mb, 1));
        mb = fmaxf(mb, __shfl_xor_sync(0xffffffffu, mb, 2));
        float mna = fmaxf(m_a, ma), mnb = fmaxf(m_b, mb);
        float ca = ex2f(m_a - mna), cb = ex2f(m_b - mnb);
        m_a = mna; m_b = mnb;

        float ra = 0.f, rb = 0.f;
        uint32_t pAh[8], pBh[8], pAl[8], pBl[8];
        #pragma unroll
        for (int nt = 0; nt < 8; nt++) {
            float p0 = ex2f(s[nt][0] - mna);
            float p1 = ex2f(s[nt][1] - mna);
            float p2 = ex2f(s[nt][2] - mnb);
            float p3 = ex2f(s[nt][3] - mnb);
            ra += p0 + p1; rb += p2 + p3;
            __half h0 = __float2half_rn(p0), h1 = __float2half_rn(p1);
            __half h2 = __float2half_rn(p2), h3 = __float2half_rn(p3);
            pAh[nt] = packh(h0, h1);
            pBh[nt] = packh(h2, h3);
            pAl[nt] = packh(__float2half_rn(p0 - __half2float(h0)),
                            __float2half_rn(p1 - __half2float(h1)));
            pBl[nt] = packh(__float2half_rn(p2 - __half2float(h2)),
                            __float2half_rn(p3 - __half2float(h3)));
        }
        ra += __shfl_xor_sync(0xffffffffu, ra, 1);
        ra += __shfl_xor_sync(0xffffffffu, ra, 2);
        rb += __shfl_xor_sync(0xffffffffu, rb, 1);
        rb += __shfl_xor_sync(0xffffffffu, rb, 2);
        l_a = l_a * ca + ra;
        l_b = l_b * cb + rb;
        #pragma unroll
        for (int dt = 0; dt < 8; dt++) {
            o[dt][0] *= ca; o[dt][1] *= ca;
            o[dt][2] *= cb; o[dt][3] *= cb;
        }

        // --- O += P @ V ---
        #pragma unroll
        for (int dt = 0; dt < 8; dt++) {
            int dr = dt * 8 + g;
            #pragma unroll
            for (int j = 0; j < 4; j++) {
                int c = j * 16 + 2 * tig;
                uint32_t bh[2], bl[2];
                bh[0] = *(const uint32_t*)&Vt[0][dr][c];
                bh[1] = *(const uint32_t*)&Vt[0][dr][c + 8];
                bl[0] = *(const uint32_t*)&Vt[1][dr][c];
                bl[1] = *(const uint32_t*)&Vt[1][dr][c + 8];
                uint32_t ah[4] = { pAh[2*j], pBh[2*j], pAh[2*j+1], pBh[2*j+1] };
                uint32_t al[4] = { pAl[2*j], pBl[2*j], pAl[2*j+1], pBl[2*j+1] };
                mma16816(o[dt], ah, bh);
                mma16816(o[dt], ah, bl);
                mma16816(o[dt], al, bh);
            }
        }
    }

    // --- epilogue: out[(b*L + l)*C + h*D + d] ---
    float inva = 1.f / l_a, invb = 1.f / l_b;
    #pragma unroll
    for (int dt = 0; dt < 8; dt++) {
        int d = dt * 8 + 2 * tig;
        if (va)
            *(float2*)&out[((size_t)(b * LL + qra)) * CC + h * DD + d] =
                make_float2(o[dt][0] * inva, o[dt][1] * inva);
        if (vb)
            *(float2*)&out[((size_t)(b * LL + qrb)) * CC + h * DD + d] =
                make_float2(o[dt][2] * invb, o[dt][3] * invb);
    }
}

// ---------------------------------------------------------------------------
// LayerNorm over C=1024, fused split-fp16 output. One block per row.
// ---------------------------------------------------------------------------
__global__ __launch_bounds__(256) void ln_split_kernel(
    const float* __restrict__ x, const float* __restrict__ gamma,
    const float* __restrict__ beta, __half* __restrict__ oh,
    __half* __restrict__ ol)
{
    const int row = blockIdx.x;
    const float* p = x + (size_t)row * CC;
    const int tid = threadIdx.x;

    float v[4], sum = 0.f, sq = 0.f;
    #pragma unroll
    for (int j = 0; j < 4; j++) {
        v[j] = p[tid + j * 256];
        sum += v[j];
        sq  = fmaf(v[j], v[j], sq);
    }
    #pragma unroll
    for (int ofs = 16; ofs; ofs >>= 1) {
        sum += __shfl_xor_sync(0xffffffffu, sum, ofs);
        sq  += __shfl_xor_sync(0xffffffffu, sq, ofs);
    }
    __shared__ float rs[8], rq[8];
    int wid = tid >> 5, lane = tid & 31;
    if (lane == 0) { rs[wid] = sum; rq[wid] = sq; }
    __syncthreads();
    if (tid == 0) {
        float a = 0.f, b2 = 0.f;
        #pragma unroll
        for (int i = 0; i < 8; i++) { a += rs[i]; b2 += rq[i]; }
        rs[0] = a; rq[0] = b2;
    }
    __syncthreads();
    sum = rs[0]; sq = rq[0];

    float mu   = sum * (1.f / CC);
    float var  = sq * (1.f / CC) - mu * mu;
    float rstd = rsqrtf(var + 1e-5f);
    #pragma unroll
    for (int j = 0; j < 4; j++) {
        int c = tid + j * 256;
        float y = (v[j] - mu) * rstd * gamma[c] + beta[c];
        __half h = __float2half_rn(y);
        oh[(size_t)row * CC + c] = h;
        ol[(size_t)row * CC + c] = __float2half_rn(y - __half2float(h));
    }
}

// ---------------------------------------------------------------------------
extern "C" void kernel_launch(void* const* d_in, const int* in_sizes, int n_in,
                              void* d_out, int out_size)
{
    const float* x     = (const float*)d_in[0];
    const float* rope  = (const float*)d_in[1];
    const float* Wqkv  = (const float*)d_in[2];
    const float* bqkv  = (const float*)d_in[3];
    const float* Wproj = (const float*)d_in[4];
    const float* bproj = (const float*)d_in[5];
    const float* gamma = (const float*)d_in[6];
    const float* beta  = (const float*)d_in[7];
    float* out = (float*)d_out;

    float  *qkv = nullptr, *att = nullptr;
    __half *xh, *xl, *qhh, *qll, *ah, *al, *wh, *wl, *ph, *pl;
    cudaGetSymbolAddress((void**)&qkv, g_qkv);
    cudaGetSymbolAddress((void**)&att, g_att);
    cudaGetSymbolAddress((void**)&xh, g_xh);
    cudaGetSymbolAddress((void**)&xl, g_xl);
    cudaGetSymbolAddress((void**)&qhh, g_qh);
    cudaGetSymbolAddress((void**)&qll, g_ql);
    cudaGetSymbolAddress((void**)&ah, g_ah);
    cudaGetSymbolAddress((void**)&al, g_al);
    cudaGetSymbolAddress((void**)&wh, g_wh);
    cudaGetSymbolAddress((void**)&wl, g_wl);
    cudaGetSymbolAddress((void**)&ph, g_ph);
    cudaGetSymbolAddress((void**)&pl, g_pl);

    const int nx = MROWS * CC;        // 8,404,992
    const int nw = CC * QKVN;         // 3,145,728
    const int np = CC * CC;           // 1,048,576
    const int nq = MROWS * QKVN;      // 25,214,976

    // 0. splits of inputs
    split_kernel<<<(nx/4 + 255)/256, 256>>>(x,     xh, xl, nx);
    split_kernel<<<(nw/4 + 255)/256, 256>>>(Wqkv,  wh, wl, nw);
    split_kernel<<<(np/4 + 255)/256, 256>>>(Wproj, ph, pl, np);

    // 1. QKV GEMM (tensor, split fp16) -> fp32 qkv
    {
        dim3 grid(QKVN / 128, (MROWS + 127) / 128);
        gemm_f16s<<<grid, 256>>>(xh, xl, wh, wl, bqkv, qkv, MROWS, QKVN, CC);
    }
    // 2. RoPE in-place (fp32)
    rope_kernel<<<(ROPE_TOTAL + 255)/256, 256>>>(qkv, rope);

    // 3. split rope'd qkv -> halves
    split_kernel<<<(nq/4 + 255)/256, 256>>>(qkv, qhh, qll, nq);

    // 4. tensor flash attention -> fp32 att ([B,L,C] layout)
    {
        dim3 grid((LL + 63) / 64, HH, BB);
        attn_f16s<<<grid, 128>>>(qhh, qll, att);
    }
    // 5. LayerNorm + split -> halves
    ln_split_kernel<<<MROWS, 256>>>(att, gamma, beta, ah, al);

    // 6. proj GEMM -> out (fp32)
    {
        dim3 grid(CC / 128, (MROWS + 127) / 128);
        gemm_f16s<<<grid, 256>>>(ah, al, ph, pl, bproj, out, MROWS, CC, CC);
    }
}

// round 7
// speedup vs baseline: 2.2761x; 1.1791x over previous
#include <cuda_runtime.h>
#include <cuda_fp16.h>
#include <math.h>
#include <stdint.h>

// Problem constants
#define BB 4
#define LL 2052
#define CC 1024
#define HH 16
#define DD 64
#define NREG 4
#define MROWS (BB*LL)          // 8208
#define QKVN (3*CC)            // 3072
#define VSTR 2056              // padded kv stride for transposed V (16B aligned)

// ---------------------------------------------------------------------------
// Device scratch
// ---------------------------------------------------------------------------
__device__ float  g_qkv[(size_t)MROWS * QKVN];     // fp32 qkv (pre-rope)
__device__ float  g_att[(size_t)MROWS * CC];       // fp32 attention output
__device__ __half g_xh[(size_t)MROWS * CC];
__device__ __half g_xl[(size_t)MROWS * CC];
__device__ __half g_qh[(size_t)MROWS * QKVN];      // split qkv (q,k used; rope applied)
__device__ __half g_ql[(size_t)MROWS * QKVN];
__device__ __half g_ah[(size_t)MROWS * CC];
__device__ __half g_al[(size_t)MROWS * CC];
__device__ __half g_wh[(size_t)CC * QKVN];         // Wqkv^T [N][K]
__device__ __half g_wl[(size_t)CC * QKVN];
__device__ __half g_ph[(size_t)CC * CC];           // Wproj^T [N][K]
__device__ __half g_pl[(size_t)CC * CC];
__device__ __half g_vth[(size_t)BB * HH * DD * VSTR];  // V^T [b,h,d][kv]
__device__ __half g_vtl[(size_t)BB * HH * DD * VSTR];

__device__ __forceinline__ float ex2f(float x) {
    float y; asm("ex2.approx.f32 %0, %1;" : "=f"(y) : "f"(x)); return y;
}
__device__ __forceinline__ uint32_t packh(__half lo, __half hi) {
    return ((uint32_t)__half_as_ushort(hi) << 16) | (uint32_t)__half_as_ushort(lo);
}
__device__ __forceinline__ void mma16816(float* d, const uint32_t* a, const uint32_t* b) {
    asm volatile(
        "mma.sync.aligned.m16n8k16.row.col.f32.f16.f16.f32 "
        "{%0,%1,%2,%3}, {%4,%5,%6,%7}, {%8,%9}, {%0,%1,%2,%3};\n"
        : "+f"(d[0]), "+f"(d[1]), "+f"(d[2]), "+f"(d[3])
        : "r"(a[0]), "r"(a[1]), "r"(a[2]), "r"(a[3]), "r"(b[0]), "r"(b[1]));
}
__device__ __forceinline__ void cp16(void* s, const void* g, int szbytes) {
    uint32_t sa = (uint32_t)__cvta_generic_to_shared(s);
    asm volatile("cp.async.cg.shared.global [%0], [%1], 16, %2;\n"
                 :: "r"(sa), "l"(g), "r"(szbytes));
}
#define CP_COMMIT asm volatile("cp.async.commit_group;\n" ::: "memory")
#define CP_WAIT1  asm volatile("cp.async.wait_group 1;\n" ::: "memory")
#define CP_WAIT0  asm volatile("cp.async.wait_group 0;\n" ::: "memory")

// ---------------------------------------------------------------------------
// Elementwise split fp32 -> (hi, lo) fp16
// ---------------------------------------------------------------------------
__global__ __launch_bounds__(256) void split_kernel(
    const float* __restrict__ src, __half* __restrict__ hi,
    __half* __restrict__ lo, int n)
{
    int i = (blockIdx.x * 256 + threadIdx.x) * 4;
    if (i >= n) return;
    float4 v = *(const float4*)(src + i);
    __half h0 = __float2half_rn(v.x), h1 = __float2half_rn(v.y);
    __half h2 = __float2half_rn(v.z), h3 = __float2half_rn(v.w);
    __half l0 = __float2half_rn(v.x - __half2float(h0));
    __half l1 = __float2half_rn(v.y - __half2float(h1));
    __half l2 = __float2half_rn(v.z - __half2float(h2));
    __half l3 = __float2half_rn(v.w - __half2float(h3));
    *(uint2*)(hi + i) = make_uint2(packh(h0, h1), packh(h2, h3));
    *(uint2*)(lo + i) = make_uint2(packh(l0, l1), packh(l2, l3));
}

// ---------------------------------------------------------------------------
// Split + transpose weights: src[K][N] fp32 -> hi/lo [N][K] fp16
// ---------------------------------------------------------------------------
__global__ __launch_bounds__(256) void split_trans_kernel(
    const float* __restrict__ src, __half* __restrict__ hi,
    __half* __restrict__ lo, int K, int N)
{
    __shared__ float t[32][33];
    int n0 = blockIdx.x * 32, k0 = blockIdx.y * 32;
    int tx = threadIdx.x, ty = threadIdx.y;
    #pragma unroll
    for (int i = ty; i < 32; i += 8)
        t[i][tx] = src[(size_t)(k0 + i) * N + n0 + tx];
    __syncthreads();
    #pragma unroll
    for (int i = ty; i < 32; i += 8) {
        float v = t[tx][i];   // = src[k0+tx][n0+i]
        __half h = __float2half_rn(v);
        size_t o = (size_t)(n0 + i) * K + k0 + tx;
        hi[o] = h;
        lo[o] = __float2half_rn(v - __half2float(h));
    }
}

// ---------------------------------------------------------------------------
// Fused RoPE + split for q,k  (s=0,1).  grid(4, B*L), block 256.
// ---------------------------------------------------------------------------
__global__ __launch_bounds__(256) void split_rope_qk(
    const float* __restrict__ qkv, const float* __restrict__ rope,
    __half* __restrict__ qh, __half* __restrict__ ql)
{
    int t = blockIdx.x * 256 + threadIdx.x;   // 0..1023
    int dp = t & 31, h = (t >> 5) & 15, s = t >> 9;
    int bl = blockIdx.y;
    int l = bl % LL;
    size_t off = ((size_t)bl * 3 + s) * CC + h * DD;
    const float* p = qkv + off;
    float x1 = p[dp], x2 = p[dp + 32];
    if (l >= NREG) {
        size_t l4 = (size_t)(l - NREG) * DD;
        float c1 = rope[l4 + dp], c2 = rope[l4 + dp + 32];
        const float* sb = rope + (size_t)(LL - NREG) * DD;
        float s1 = sb[l4 + dp], s2 = sb[l4 + dp + 32];
        float y1 = x1 * c1 - x2 * s1;
        float y2 = x2 * c2 + x1 * s2;
        x1 = y1; x2 = y2;
    }
    __half h1 = __float2half_rn(x1), h2 = __float2half_rn(x2);
    qh[off + dp]      = h1;
    ql[off + dp]      = __float2half_rn(x1 - __half2float(h1));
    qh[off + dp + 32] = h2;
    ql[off + dp + 32] = __float2half_rn(x2 - __half2float(h2));
}

// ---------------------------------------------------------------------------
// V transpose + split: qkv v-slice [b][l][h*64+d] -> vth/vtl [(b*16+h)*64+d][l]
// grid(ceil(L/32), 2, 64), block(32,8)
// ---------------------------------------------------------------------------
__global__ __launch_bounds__(256) void v_trans_split(
    const float* __restrict__ qkv, __half* __restrict__ vth,
    __half* __restrict__ vtl)
{
    __shared__ float t[32][33];
    int l0 = blockIdx.x * 32, d0 = blockIdx.y * 32;
    int b = blockIdx.z >> 4, h = blockIdx.z & 15;
    int tx = threadIdx.x, ty = threadIdx.y;
    #pragma unroll
    for (int i = ty; i < 32; i += 8) {
        int l = l0 + i;
        t[i][tx] = (l < LL)
            ? qkv[(((size_t)(b * LL + l)) * 3 + 2) * CC + h * DD + d0 + tx] : 0.f;
    }
    __syncthreads();
    #pragma unroll
    for (int i = ty; i < 32; i += 8) {
        int l = l0 + tx;
        if (l < LL) {
            float v = t[tx][i];
            __half hh = __float2half_rn(v);
            size_t o = ((size_t)((b * HH + h) * DD + d0 + i)) * VSTR + l;
            vth[o] = hh;
            vtl[o] = __float2half_rn(v - __half2float(hh));
        }
    }
}

// ---------------------------------------------------------------------------
// Pipelined split-fp16 GEMM: C = (Ah+Al)[M,K] @ (Bh+Bl)[N,K]^T + bias
// Both operands row-major over K. BM=BN=128, BK=32, 256 thr, 2-stage cp.async.
// ---------------------------------------------------------------------------
#define ASTR 40
#define GTILE (128 * ASTR)   // halves per (stage, matrix, hl) tile

__global__ __launch_bounds__(256) void gemm_f16s(
    const __half* __restrict__ Ah, const __half* __restrict__ Al,
    const __half* __restrict__ Bh, const __half* __restrict__ Bl,
    const float* __restrict__ bias, float* __restrict__ C,
    int M, int N, int K)
{
    extern __shared__ __half sm[];
    // tile(st, mat, hl) = sm + ((st*2+mat)*2 + hl) * GTILE

    const int tid = threadIdx.x, lane = tid & 31, wid = tid >> 5;
    const int g = lane >> 2, tig = lane & 3;
    const int row0 = blockIdx.y * 128, col0 = blockIdx.x * 128;
    const int wm = (wid & 1) * 64, wn = (wid >> 1) * 32;

    const int arow = tid >> 1, aseg = (tid & 1) * 16;
    const bool avalid = (row0 + arow) < M;
    const size_t garow = avalid ? (size_t)(row0 + arow) : 0;
    const size_t gbrow = (size_t)(col0 + arow);

    float acc[4][4][4];
    #pragma unroll
    for (int mt = 0; mt < 4; mt++)
        #pragma unroll
        for (int nt = 0; nt < 4; nt++)
            #pragma unroll
            for (int r = 0; r < 4; r++) acc[mt][nt][r] = 0.f;

    auto stage = [&](int st, int kt) {
        __half* tA0 = sm + ((st * 2 + 0) * 2 + 0) * GTILE;
        __half* tA1 = sm + ((st * 2 + 0) * 2 + 1) * GTILE;
        __half* tB0 = sm + ((st * 2 + 1) * 2 + 0) * GTILE;
        __half* tB1 = sm + ((st * 2 + 1) * 2 + 1) * GTILE;
        int sz = avalid ? 16 : 0;
        size_t ga = garow * K + kt + aseg;
        cp16(tA0 + arow * ASTR + aseg,     Ah + ga,     sz);
        cp16(tA0 + arow * ASTR + aseg + 8, Ah + ga + 8, sz);
        cp16(tA1 + arow * ASTR + aseg,     Al + ga,     sz);
        cp16(tA1 + arow * ASTR + aseg + 8, Al + ga + 8, sz);
        size_t gb = gbrow * K + kt + aseg;
        cp16(tB0 + arow * ASTR + aseg,     Bh + gb,     16);
        cp16(tB0 + arow * ASTR + aseg + 8, Bh + gb + 8, 16);
        cp16(tB1 + arow * ASTR + aseg,     Bl + gb,     16);
        cp16(tB1 + arow * ASTR + aseg + 8, Bl + gb + 8, 16);
    };

    const int niter = K >> 5;
    stage(0, 0);
    CP_COMMIT;

    for (int i = 0; i < niter; i++) {
        if (i + 1 < niter) { stage((i + 1) & 1, (i + 1) * 32); CP_COMMIT; CP_WAIT1; }
        else CP_WAIT0;
        __syncthreads();

        const int st = i & 1;
        const __half* tA0 = sm + ((st * 2 + 0) * 2 + 0) * GTILE;
        const __half* tA1 = sm + ((st * 2 + 0) * 2 + 1) * GTILE;
        const __half* tB0 = sm + ((st * 2 + 1) * 2 + 0) * GTILE;
        const __half* tB1 = sm + ((st * 2 + 1) * 2 + 1) * GTILE;

        #pragma unroll
        for (int ks = 0; ks < 2; ks++) {
            const int c = ks * 16 + 2 * tig;
            uint32_t afh[4][4], afl[4][4], bfh[4][2], bfl[4][2];
            #pragma unroll
            for (int mt = 0; mt < 4; mt++) {
                int r = wm + mt * 16 + g;
                afh[mt][0] = *(const uint32_t*)&tA0[r * ASTR + c];
                afh[mt][1] = *(const uint32_t*)&tA0[(r + 8) * ASTR + c];
                afh[mt][2] = *(const uint32_t*)&tA0[r * ASTR + c + 8];
                afh[mt][3] = *(const uint32_t*)&tA0[(r + 8) * ASTR + c + 8];
                afl[mt][0] = *(const uint32_t*)&tA1[r * ASTR + c];
                afl[mt][1] = *(const uint32_t*)&tA1[(r + 8) * ASTR + c];
                afl[mt][2] = *(const uint32_t*)&tA1[r * ASTR + c + 8];
                afl[mt][3] = *(const uint32_t*)&tA1[(r + 8) * ASTR + c + 8];
            }
            #pragma unroll
            for (int nt = 0; nt < 4; nt++) {
                int n = wn + nt * 8 + g;
                bfh[nt][0] = *(const uint32_t*)&tB0[n * ASTR + c];
                bfh[nt][1] = *(const uint32_t*)&tB0[n * ASTR + c + 8];
                bfl[nt][0] = *(const uint32_t*)&tB1[n * ASTR + c];
                bfl[nt][1] = *(const uint32_t*)&tB1[n * ASTR + c + 8];
            }
            #pragma unroll
            for (int mt = 0; mt < 4; mt++)
                #pragma unroll
                for (int nt = 0; nt < 4; nt++) {
                    mma16816(acc[mt][nt], afh[mt], bfh[nt]);
                    mma16816(acc[mt][nt], afh[mt], bfl[nt]);
                    mma16816(acc[mt][nt], afl[mt], bfh[nt]);
                }
        }
        __syncthreads();
    }

    #pragma unroll
    for (int mt = 0; mt < 4; mt++) {
        int ra = row0 + wm + mt * 16 + g;
        int rb = ra + 8;
        #pragma unroll
        for (int nt = 0; nt < 4; nt++) {
            int cc = col0 + wn + nt * 8 + 2 * tig;
            float b0 = bias[cc], b1 = bias[cc + 1];
            if (ra < M)
                *(float2*)&C[(size_t)ra * N + cc] =
                    make_float2(acc[mt][nt][0] + b0, acc[mt][nt][1] + b1);
            if (rb < M)
                *(float2*)&C[(size_t)rb * N + cc] =
                    make_float2(acc[mt][nt][2] + b0, acc[mt][nt][3] + b1);
        }
    }
}
#define GEMM_SMEM (8 * GTILE * (int)sizeof(__half))   // 81920 B

// ---------------------------------------------------------------------------
// Pipelined tensor-core flash attention, split fp16.
// 128 threads (4 warps), Br=64, Bc=64, D=64; 2-stage cp.async K/V staging.
// ---------------------------------------------------------------------------
#define KSTR 72
#define ATILE (64 * KSTR)

__global__ __launch_bounds__(128) void attn_f16s(
    const __half* __restrict__ qh, const __half* __restrict__ ql,
    const __half* __restrict__ vth, const __half* __restrict__ vtl,
    float* __restrict__ out)
{
    extern __shared__ __half sm[];
    const int qt = blockIdx.x, h = blockIdx.y, b = blockIdx.z;
    const int tid = threadIdx.x, lane = tid & 31, wid = tid >> 5;
    const int g = lane >> 2, tig = lane & 3;
    const size_t rstr = QKVN;
    const __half* qbh = qh + (size_t)b * LL * rstr + h * DD;
    const __half* qbl = ql + (size_t)b * LL * rstr + h * DD;
    const __half* kbh = qbh + CC;
    const __half* kbl = qbl + CC;
    const __half* vbh = vth + (size_t)((b * HH + h) * DD) * VSTR;
    const __half* vbl = vtl + (size_t)((b * HH + h) * DD) * VSTR;

    // ---- Q fragments (register resident) ----
    uint32_t qfh[4][4], qfl[4][4];
    const int q0 = qt * 64 + wid * 16;
    const int qra = q0 + g, qrb = qra + 8;
    const bool va = qra < LL, vb = qrb < LL;
    #pragma unroll
    for (int kt = 0; kt < 4; kt++) {
        int c = kt * 16 + 2 * tig;
        qfh[kt][0] = va ? *(const uint32_t*)(qbh + (size_t)qra * rstr + c) : 0u;
        qfh[kt][1] = vb ? *(const uint32_t*)(qbh + (size_t)qrb * rstr + c) : 0u;
        qfh[kt][2] = va ? *(const uint32_t*)(qbh + (size_t)qra * rstr + c + 8) : 0u;
        qfh[kt][3] = vb ? *(const uint32_t*)(qbh + (size_t)qrb * rstr + c + 8) : 0u;
        qfl[kt][0] = va ? *(const uint32_t*)(qbl + (size_t)qra * rstr + c) : 0u;
        qfl[kt][1] = vb ? *(const uint32_t*)(qbl + (size_t)qrb * rstr + c) : 0u;
        qfl[kt][2] = va ? *(const uint32_t*)(qbl + (size_t)qra * rstr + c + 8) : 0u;
        qfl[kt][3] = vb ? *(const uint32_t*)(qbl + (size_t)qrb * rstr + c + 8) : 0u;
    }

    float m_a = -1e30f, m_b = -1e30f, l_a = 0.f, l_b = 0.f;
    float o[8][4];
    #pragma unroll
    for (int dt = 0; dt < 8; dt++)
        #pragma unroll
        for (int r = 0; r < 4; r++) o[dt][r] = 0.f;

    const float sc = 0.125f * 1.4426950408889634f;
    const int nkt = (LL + 63) / 64;   // 33

    auto stage = [&](int st, int kvb) {
        __half* KH = sm + st * 4 * ATILE;
        __half* KL = KH + ATILE;
        __half* VH = KL + ATILE;
        __half* VL = VH + ATILE;
        int row = tid >> 1, seg = (tid & 1) * 32;
        {
            int lkv = kvb + row;
            int sz = (lkv < LL) ? 16 : 0;
            size_t go = (size_t)(sz ? lkv : 0) * rstr + seg;
            #pragma unroll
            for (int c = 0; c < 4; c++) {
                cp16(KH + row * KSTR + seg + c * 8, kbh + go + c * 8, sz);
                cp16(KL + row * KSTR + seg + c * 8, kbl + go + c * 8, sz);
            }
        }
        {
            #pragma unroll
            for (int c = 0; c < 4; c++) {
                int rem = LL - (kvb + seg + c * 8);
                int sz = rem >= 8 ? 16 : (rem > 0 ? rem * 2 : 0);
                size_t go = sz ? ((size_t)row * VSTR + kvb + seg + c * 8) : 0;
                cp16(VH + row * KSTR + seg + c * 8, vbh + go, sz);
                cp16(VL + row * KSTR + seg + c * 8, vbl + go, sz);
            }
        }
    };

    stage(0, 0);
    CP_COMMIT;

    for (int t = 0; t < nkt; ++t) {
        if (t + 1 < nkt) { stage((t + 1) & 1, (t + 1) * 64); CP_COMMIT; CP_WAIT1; }
        else CP_WAIT0;
        __syncthreads();

        const int st = t & 1;
        const __half* KH = sm + st * 4 * ATILE;
        const __half* KL = KH + ATILE;
        const __half* VH = KL + ATILE;
        const __half* VL = VH + ATILE;
        const int kvb = t * 64;

        // --- S = Q @ K^T ---
        float s[8][4];
        #pragma unroll
        for (int nt = 0; nt < 8; nt++)
            #pragma unroll
            for (int r = 0; r < 4; r++) s[nt][r] = 0.f;

        #pragma unroll
        for (int nt = 0; nt < 8; nt++) {
            int kr = nt * 8 + g;
            #pragma unroll
            for (int kt = 0; kt < 4; kt++) {
                int c = kt * 16 + 2 * tig;
                uint32_t bh[2], bl[2];
                bh[0] = *(const uint32_t*)&KH[kr * KSTR + c];
                bh[1] = *(const uint32_t*)&KH[kr * KSTR + c + 8];
                bl[0] = *(const uint32_t*)&KL[kr * KSTR + c];
                bl[1] = *(const uint32_t*)&KL[kr * KSTR + c + 8];
                mma16816(s[nt], qfh[kt], bh);
                mma16816(s[nt], qfh[kt], bl);
                mma16816(s[nt], qfl[kt], bh);
            }
        }
        #pragma unroll
        for (int nt = 0; nt < 8; nt++)
            #pragma unroll
            for (int r = 0; r < 4; r++) s[nt][r] *= sc;

        if (t == nkt - 1) {
            #pragma unroll
            for (int nt = 0; nt < 8; nt++) {
                int kv0 = kvb + nt * 8 + 2 * tig;
                if (kv0 >= LL)     { s[nt][0] = -1e30f; s[nt][2] = -1e30f; }
                if (kv0 + 1 >= LL) { s[nt][1] = -1e30f; s[nt][3] = -1e30f; }
            }
        }

        // --- online softmax ---
        float ma = -1e30f, mb = -1e30f;
        #pragma unroll
        for (int nt = 0; nt < 8; nt++) {
            ma = fmaxf(ma, fmaxf(s[nt][0], s[nt][1]));
            mb = fmaxf(mb, fmaxf(s[nt][2], s[nt][3]));
        }
        ma = fmaxf(ma, __shfl_xor_sync(0xffffffffu, ma, 1));
        ma = fmaxf(ma, __shfl_xor_sync(0xffffffffu, ma, 2));
        mb = fmaxf(mb, __shfl_xor_sync(0xffffffffu, mb, 1));
        mb = fmaxf(mb, __shfl_xor_sync(0xffffffffu, mb, 2));
        float mna = fmaxf(m_a, ma), mnb = fmaxf(m_b, mb);
        float ca = ex2f(m_a - mna), cb = ex2f(m_b - mnb);
        m_a = mna; m_b = mnb;

        float ra = 0.f, rb = 0.f;
        uint32_t pAh[8], pBh[8], pAl[8], pBl[8];
        #pragma unroll
        for (int nt = 0; nt < 8; nt++) {
            float p0 = ex2f(s[nt][0] - mna);
            float p1 = ex2f(s[nt][1] - mna);
            float p2 = ex2f(s[nt][2] - mnb);
            float p3 = ex2f(s[nt][3] - mnb);
            ra += p0 + p1; rb += p2 + p3;
            __half h0 = __float2half_rn(p0), h1 = __float2half_rn(p1);
            __half h2 = __float2half_rn(p2), h3 = __float2half_rn(p3);
            pAh[nt] = packh(h0, h1);
            pBh[nt] = packh(h2, h3);
            pAl[nt] = packh(__float2half_rn(p0 - __half2float(h0)),
                            __float2half_rn(p1 - __half2float(h1)));
            pBl[nt] = packh(__float2half_rn(p2 - __half2float(h2)),
                            __float2half_rn(p3 - __half2float(h3)));
        }
        ra += __shfl_xor_sync(0xffffffffu, ra, 1);
        ra += __shfl_xor_sync(0xffffffffu, ra, 2);
        rb += __shfl_xor_sync(0xffffffffu, rb, 1);
        rb += __shfl_xor_sync(0xffffffffu, rb, 2);
        l_a = l_a * ca + ra;
        l_b = l_b * cb + rb;
        #pragma unroll
        for (int dt = 0; dt < 8; dt++) {
            o[dt][0] *= ca; o[dt][1] *= ca;
            o[dt][2] *= cb; o[dt][3] *= cb;
        }

        // --- O += P @ V ---
        #pragma unroll
        for (int dt = 0; dt < 8; dt++) {
            int dr = dt * 8 + g;
            #pragma unroll
            for (int j = 0; j < 4; j++) {
                int c = j * 16 + 2 * tig;
                uint32_t bh[2], bl[2];
                bh[0] = *(const uint32_t*)&VH[dr * KSTR + c];
                bh[1] = *(const uint32_t*)&VH[dr * KSTR + c + 8];
                bl[0] = *(const uint32_t*)&VL[dr * KSTR + c];
                bl[1] = *(const uint32_t*)&VL[dr * KSTR + c + 8];
                uint32_t ah[4] = { pAh[2*j], pBh[2*j], pAh[2*j+1], pBh[2*j+1] };
                uint32_t al[4] = { pAl[2*j], pBl[2*j], pAl[2*j+1], pBl[2*j+1] };
                mma16816(o[dt], ah, bh);
                mma16816(o[dt], ah, bl);
                mma16816(o[dt], al, bh);
            }
        }
        __syncthreads();
    }

    float inva = 1.f / l_a, invb = 1.f / l_b;
    #pragma unroll
    for (int dt = 0; dt < 8; dt++) {
        int d = dt * 8 + 2 * tig;
        if (va)
            *(float2*)&out[((size_t)(b * LL + qra)) * CC + h * DD + d] =
                make_float2(o[dt][0] * inva, o[dt][1] * inva);
        if (vb)
            *(float2*)&out[((size_t)(b * LL + qrb)) * CC + h * DD + d] =
                make_float2(o[dt][2] * invb, o[dt][3] * invb);
    }
}
#define ATTN_SMEM (8 * ATILE * (int)sizeof(__half))   // 73728 B

// ---------------------------------------------------------------------------
// LayerNorm over C=1024, fused split-fp16 output. One block per row.
// ---------------------------------------------------------------------------
__global__ __launch_bounds__(256) void ln_split_kernel(
    const float* __restrict__ x, const float* __restrict__ gamma,
    const float* __restrict__ beta, __half* __restrict__ oh,
    __half* __restrict__ ol)
{
    const int row = blockIdx.x;
    const float* p = x + (size_t)row * CC;
    const int tid = threadIdx.x;

    float v[4], sum = 0.f, sq = 0.f;
    #pragma unroll
    for (int j = 0; j < 4; j++) {
        v[j] = p[tid + j * 256];
        sum += v[j];
        sq  = fmaf(v[j], v[j], sq);
    }
    #pragma unroll
    for (int ofs = 16; ofs; ofs >>= 1) {
        sum += __shfl_xor_sync(0xffffffffu, sum, ofs);
        sq  += __shfl_xor_sync(0xffffffffu, sq, ofs);
    }
    __shared__ float rs[8], rq[8];
    int wid = tid >> 5, lane = tid & 31;
    if (lane == 0) { rs[wid] = sum; rq[wid] = sq; }
    __syncthreads();
    if (tid == 0) {
        float a = 0.f, b2 = 0.f;
        #pragma unroll
        for (int i = 0; i < 8; i++) { a += rs[i]; b2 += rq[i]; }
        rs[0] = a; rq[0] = b2;
    }
    __syncthreads();
    sum = rs[0]; sq = rq[0];

    float mu   = sum * (1.f / CC);
    float var  = sq * (1.f / CC) - mu * mu;
    float rstd = rsqrtf(var + 1e-5f);
    #pragma unroll
    for (int j = 0; j < 4; j++) {
        int c = tid + j * 256;
        float y = (v[j] - mu) * rstd * gamma[c] + beta[c];
        __half h = __float2half_rn(y);
        oh[(size_t)row * CC + c] = h;
        ol[(size_t)row * CC + c] = __float2half_rn(y - __half2float(h));
    }
}

// ---------------------------------------------------------------------------
extern "C" void kernel_launch(void* const* d_in, const int* in_sizes, int n_in,
                              void* d_out, int out_size)
{
    const float* x     = (const float*)d_in[0];
    const float* rope  = (const float*)d_in[1];
    const float* Wqkv  = (const float*)d_in[2];
    const float* bqkv  = (const float*)d_in[3];
    const float* Wproj = (const float*)d_in[4];
    const float* bproj = (const float*)d_in[5];
    const float* gamma = (const float*)d_in[6];
    const float* beta  = (const float*)d_in[7];
    float* out = (float*)d_out;

    float  *qkv, *att;
    __half *xh, *xl, *qhh, *qll, *ah, *al, *wh, *wl, *ph, *pl, *vth, *vtl;
    cudaGetSymbolAddress((void**)&qkv, g_qkv);
    cudaGetSymbolAddress((void**)&att, g_att);
    cudaGetSymbolAddress((void**)&xh, g_xh);
    cudaGetSymbolAddress((void**)&xl, g_xl);
    cudaGetSymbolAddress((void**)&qhh, g_qh);
    cudaGetSymbolAddress((void**)&qll, g_ql);
    cudaGetSymbolAddress((void**)&ah, g_ah);
    cudaGetSymbolAddress((void**)&al, g_al);
    cudaGetSymbolAddress((void**)&wh, g_wh);
    cudaGetSymbolAddress((void**)&wl, g_wl);
    cudaGetSymbolAddress((void**)&ph, g_ph);
    cudaGetSymbolAddress((void**)&pl, g_pl);
    cudaGetSymbolAddress((void**)&vth, g_vth);
    cudaGetSymbolAddress((void**)&vtl, g_vtl);

    cudaFuncSetAttribute(gemm_f16s,
        cudaFuncAttributeMaxDynamicSharedMemorySize, GEMM_SMEM);
    cudaFuncSetAttribute(attn_f16s,
        cudaFuncAttributeMaxDynamicSharedMemorySize, ATTN_SMEM);

    const int nx = MROWS * CC;

    // 0. splits (x elementwise; weights transposed)
    split_kernel<<<(nx/4 + 255)/256, 256>>>(x, xh, xl, nx);
    split_trans_kernel<<<dim3(QKVN/32, CC/32), dim3(32, 8)>>>(Wqkv, wh, wl, CC, QKVN);
    split_trans_kernel<<<dim3(CC/32,  CC/32), dim3(32, 8)>>>(Wproj, ph, pl, CC, CC);

    // 1. QKV GEMM -> fp32 qkv
    {
        dim3 grid(QKVN / 128, (MROWS + 127) / 128);
        gemm_f16s<<<grid, 256, GEMM_SMEM>>>(xh, xl, wh, wl, bqkv, qkv, MROWS, QKVN, CC);
    }
    // 2. fused RoPE + split (q,k) and V transpose + split
    split_rope_qk<<<dim3(4, MROWS), 256>>>(qkv, rope, qhh, qll);
    v_trans_split<<<dim3((LL + 31)/32, 2, BB*HH), dim3(32, 8)>>>(qkv, vth, vtl);

    // 3. pipelined flash attention -> fp32 att ([B,L,C] layout)
    {
        dim3 grid((LL + 63) / 64, HH, BB);
        attn_f16s<<<grid, 128, ATTN_SMEM>>>(qhh, qll, vth, vtl, att);
    }
    // 4. LayerNorm + split
    ln_split_kernel<<<MROWS, 256>>>(att, gamma, beta, ah, al);

    // 5. proj GEMM -> out
    {
        dim3 grid(CC / 128, (MROWS + 127) / 128);
        gemm_f16s<<<grid, 256, GEMM_SMEM>>>(ah, al, ph, pl, bproj, out, MROWS, CC, CC);
    }
}

// round 9
// speedup vs baseline: 2.7077x; 1.1897x over previous
#include <cuda_runtime.h>
#include <cuda_fp16.h>
#include <math.h>
#include <stdint.h>

// Problem constants
#define BB 4
#define LL 2052
#define CC 1024
#define HH 16
#define DD 64
#define NREG 4
#define MROWS (BB*LL)          // 8208
#define QKVN (3*CC)            // 3072
#define VSTR 2056              // padded kv stride for transposed V (16B aligned)

// ---------------------------------------------------------------------------
// Device scratch
// ---------------------------------------------------------------------------
__device__ float  g_qkv[(size_t)MROWS * QKVN];     // fp32 qkv (pre-rope)
__device__ float  g_att[(size_t)MROWS * CC];       // fp32 attention output
__device__ __half g_xh[(size_t)MROWS * CC];
__device__ __half g_xl[(size_t)MROWS * CC];
__device__ __half g_qh[(size_t)MROWS * QKVN];      // split qkv (q,k used; rope applied)
__device__ __half g_ql[(size_t)MROWS * QKVN];
__device__ __half g_ah[(size_t)MROWS * CC];
__device__ __half g_al[(size_t)MROWS * CC];
__device__ __half g_wh[(size_t)CC * QKVN];         // Wqkv^T [N][K]
__device__ __half g_wl[(size_t)CC * QKVN];
__device__ __half g_ph[(size_t)CC * CC];           // Wproj^T [N][K]
__device__ __half g_pl[(size_t)CC * CC];
__device__ __half g_vth[(size_t)BB * HH * DD * VSTR];  // V^T [b,h,d][kv]
__device__ __half g_vtl[(size_t)BB * HH * DD * VSTR];

__device__ __forceinline__ float ex2f(float x) {
    float y; asm("ex2.approx.f32 %0, %1;" : "=f"(y) : "f"(x)); return y;
}
__device__ __forceinline__ uint32_t packh(__half lo, __half hi) {
    return ((uint32_t)__half_as_ushort(hi) << 16) | (uint32_t)__half_as_ushort(lo);
}
__device__ __forceinline__ void mma16816(float* d, const uint32_t* a, const uint32_t* b) {
    asm volatile(
        "mma.sync.aligned.m16n8k16.row.col.f32.f16.f16.f32 "
        "{%0,%1,%2,%3}, {%4,%5,%6,%7}, {%8,%9}, {%0,%1,%2,%3};\n"
        : "+f"(d[0]), "+f"(d[1]), "+f"(d[2]), "+f"(d[3])
        : "r"(a[0]), "r"(a[1]), "r"(a[2]), "r"(a[3]), "r"(b[0]), "r"(b[1]));
}
__device__ __forceinline__ void cp16(void* s, const void* g, int szbytes) {
    uint32_t sa = (uint32_t)__cvta_generic_to_shared(s);
    asm volatile("cp.async.cg.shared.global [%0], [%1], 16, %2;\n"
                 :: "r"(sa), "l"(g), "r"(szbytes));
}
#define CP_COMMIT asm volatile("cp.async.commit_group;\n" ::: "memory")
#define CP_WAIT1  asm volatile("cp.async.wait_group 1;\n" ::: "memory")
#define CP_WAIT0  asm volatile("cp.async.wait_group 0;\n" ::: "memory")

// ---------------------------------------------------------------------------
// Elementwise split fp32 -> (hi, lo) fp16
// ---------------------------------------------------------------------------
__global__ __launch_bounds__(256) void split_kernel(
    const float* __restrict__ src, __half* __restrict__ hi,
    __half* __restrict__ lo, int n)
{
    int i = (blockIdx.x * 256 + threadIdx.x) * 4;
    if (i >= n) return;
    float4 v = *(const float4*)(src + i);
    __half h0 = __float2half_rn(v.x), h1 = __float2half_rn(v.y);
    __half h2 = __float2half_rn(v.z), h3 = __float2half_rn(v.w);
    __half l0 = __float2half_rn(v.x - __half2float(h0));
    __half l1 = __float2half_rn(v.y - __half2float(h1));
    __half l2 = __float2half_rn(v.z - __half2float(h2));
    __half l3 = __float2half_rn(v.w - __half2float(h3));
    *(uint2*)(hi + i) = make_uint2(packh(h0, h1), packh(h2, h3));
    *(uint2*)(lo + i) = make_uint2(packh(l0, l1), packh(l2, l3));
}

// ---------------------------------------------------------------------------
// Split + transpose weights: src[K][N] fp32 -> hi/lo [N][K] fp16
// ---------------------------------------------------------------------------
__global__ __launch_bounds__(256) void split_trans_kernel(
    const float* __restrict__ src, __half* __restrict__ hi,
    __half* __restrict__ lo, int K, int N)
{
    __shared__ float t[32][33];
    int n0 = blockIdx.x * 32, k0 = blockIdx.y * 32;
    int tx = threadIdx.x, ty = threadIdx.y;
    #pragma unroll
    for (int i = ty; i < 32; i += 8)
        t[i][tx] = src[(size_t)(k0 + i) * N + n0 + tx];
    __syncthreads();
    #pragma unroll
    for (int i = ty; i < 32; i += 8) {
        float v = t[tx][i];   // = src[k0+tx][n0+i]
        __half h = __float2half_rn(v);
        size_t o = (size_t)(n0 + i) * K + k0 + tx;
        hi[o] = h;
        lo[o] = __float2half_rn(v - __half2float(h));
    }
}

// ---------------------------------------------------------------------------
// Fused RoPE + split for q,k  (s=0,1).  grid(4, B*L), block 256.
// ---------------------------------------------------------------------------
__global__ __launch_bounds__(256) void split_rope_qk(
    const float* __restrict__ qkv, const float* __restrict__ rope,
    __half* __restrict__ qh, __half* __restrict__ ql)
{
    int t = blockIdx.x * 256 + threadIdx.x;   // 0..1023
    int dp = t & 31, h = (t >> 5) & 15, s = t >> 9;
    int bl = blockIdx.y;
    int l = bl % LL;
    size_t off = ((size_t)bl * 3 + s) * CC + h * DD;
    const float* p = qkv + off;
    float x1 = p[dp], x2 = p[dp + 32];
    if (l >= NREG) {
        size_t l4 = (size_t)(l - NREG) * DD;
        float c1 = rope[l4 + dp], c2 = rope[l4 + dp + 32];
        const float* sb = rope + (size_t)(LL - NREG) * DD;
        float s1 = sb[l4 + dp], s2 = sb[l4 + dp + 32];
        float y1 = x1 * c1 - x2 * s1;
        float y2 = x2 * c2 + x1 * s2;
        x1 = y1; x2 = y2;
    }
    __half h1 = __float2half_rn(x1), h2 = __float2half_rn(x2);
    qh[off + dp]      = h1;
    ql[off + dp]      = __float2half_rn(x1 - __half2float(h1));
    qh[off + dp + 32] = h2;
    ql[off + dp + 32] = __float2half_rn(x2 - __half2float(h2));
}

// ---------------------------------------------------------------------------
// V transpose + split: qkv v-slice [b][l][h*64+d] -> vth/vtl [(b*16+h)*64+d][l]
// grid(ceil(L/32), 2, 64), block(32,8)
// ---------------------------------------------------------------------------
__global__ __launch_bounds__(256) void v_trans_split(
    const float* __restrict__ qkv, __half* __restrict__ vth,
    __half* __restrict__ vtl)
{
    __shared__ float t[32][33];
    int l0 = blockIdx.x * 32, d0 = blockIdx.y * 32;
    int b = blockIdx.z >> 4, h = blockIdx.z & 15;
    int tx = threadIdx.x, ty = threadIdx.y;
    #pragma unroll
    for (int i = ty; i < 32; i += 8) {
        int l = l0 + i;
        t[i][tx] = (l < LL)
            ? qkv[(((size_t)(b * LL + l)) * 3 + 2) * CC + h * DD + d0 + tx] : 0.f;
    }
    __syncthreads();
    #pragma unroll
    for (int i = ty; i < 32; i += 8) {
        int l = l0 + tx;
        if (l < LL) {
            float v = t[tx][i];
            __half hh = __float2half_rn(v);
            size_t o = ((size_t)((b * HH + h) * DD + d0 + i)) * VSTR + l;
            vth[o] = hh;
            vtl[o] = __float2half_rn(v - __half2float(hh));
        }
    }
}

// ---------------------------------------------------------------------------
// Pipelined split-fp16 GEMM: C = (Ah+Al)[M,K] @ (Bh+Bl)[N,K]^T + bias
// BM=BN=128, BK=32, 256 thr, 2-stage cp.async, forced 2 CTAs/SM.
// ---------------------------------------------------------------------------
#define ASTR 40
#define GTILE (128 * ASTR)

__global__ __launch_bounds__(256, 2) void gemm_f16s(
    const __half* __restrict__ Ah, const __half* __restrict__ Al,
    const __half* __restrict__ Bh, const __half* __restrict__ Bl,
    const float* __restrict__ bias, float* __restrict__ C,
    int M, int N, int K)
{
    extern __shared__ __half sm[];

    const int tid = threadIdx.x, lane = tid & 31, wid = tid >> 5;
    const int g = lane >> 2, tig = lane & 3;
    const int row0 = blockIdx.y * 128, col0 = blockIdx.x * 128;
    const int wm = (wid & 1) * 64, wn = (wid >> 1) * 32;

    const int arow = tid >> 1, aseg = (tid & 1) * 16;
    const bool avalid = (row0 + arow) < M;
    const size_t garow = avalid ? (size_t)(row0 + arow) : 0;
    const size_t gbrow = (size_t)(col0 + arow);

    float acc[4][4][4];
    #pragma unroll
    for (int mt = 0; mt < 4; mt++)
        #pragma unroll
        for (int nt = 0; nt < 4; nt++)
            #pragma unroll
            for (int r = 0; r < 4; r++) acc[mt][nt][r] = 0.f;

    auto stage = [&](int st, int kt) {
        __half* tA0 = sm + ((st * 2 + 0) * 2 + 0) * GTILE;
        __half* tA1 = sm + ((st * 2 + 0) * 2 + 1) * GTILE;
        __half* tB0 = sm + ((st * 2 + 1) * 2 + 0) * GTILE;
        __half* tB1 = sm + ((st * 2 + 1) * 2 + 1) * GTILE;
        int sz = avalid ? 16 : 0;
        size_t ga = garow * K + kt + aseg;
        cp16(tA0 + arow * ASTR + aseg,     Ah + ga,     sz);
        cp16(tA0 + arow * ASTR + aseg + 8, Ah + ga + 8, sz);
        cp16(tA1 + arow * ASTR + aseg,     Al + ga,     sz);
        cp16(tA1 + arow * ASTR + aseg + 8, Al + ga + 8, sz);
        size_t gb = gbrow * K + kt + aseg;
        cp16(tB0 + arow * ASTR + aseg,     Bh + gb,     16);
        cp16(tB0 + arow * ASTR + aseg + 8, Bh + gb + 8, 16);
        cp16(tB1 + arow * ASTR + aseg,     Bl + gb,     16);
        cp16(tB1 + arow * ASTR + aseg + 8, Bl + gb + 8, 16);
    };

    const int niter = K >> 5;
    stage(0, 0);
    CP_COMMIT;

    for (int i = 0; i < niter; i++) {
        if (i + 1 < niter) { stage((i + 1) & 1, (i + 1) * 32); CP_COMMIT; CP_WAIT1; }
        else CP_WAIT0;
        __syncthreads();

        const int st = i & 1;
        const __half* tA0 = sm + ((st * 2 + 0) * 2 + 0) * GTILE;
        const __half* tA1 = sm + ((st * 2 + 0) * 2 + 1) * GTILE;
        const __half* tB0 = sm + ((st * 2 + 1) * 2 + 0) * GTILE;
        const __half* tB1 = sm + ((st * 2 + 1) * 2 + 1) * GTILE;

        #pragma unroll
        for (int ks = 0; ks < 2; ks++) {
            const int c = ks * 16 + 2 * tig;
            uint32_t afh[4][4], afl[4][4], bfh[4][2], bfl[4][2];
            #pragma unroll
            for (int mt = 0; mt < 4; mt++) {
                int r = wm + mt * 16 + g;
                afh[mt][0] = *(const uint32_t*)&tA0[r * ASTR + c];
                afh[mt][1] = *(const uint32_t*)&tA0[(r + 8) * ASTR + c];
                afh[mt][2] = *(const uint32_t*)&tA0[r * ASTR + c + 8];
                afh[mt][3] = *(const uint32_t*)&tA0[(r + 8) * ASTR + c + 8];
                afl[mt][0] = *(const uint32_t*)&tA1[r * ASTR + c];
                afl[mt][1] = *(const uint32_t*)&tA1[(r + 8) * ASTR + c];
                afl[mt][2] = *(const uint32_t*)&tA1[r * ASTR + c + 8];
                afl[mt][3] = *(const uint32_t*)&tA1[(r + 8) * ASTR + c + 8];
            }
            #pragma unroll
            for (int nt = 0; nt < 4; nt++) {
                int n = wn + nt * 8 + g;
                bfh[nt][0] = *(const uint32_t*)&tB0[n * ASTR + c];
                bfh[nt][1] = *(const uint32_t*)&tB0[n * ASTR + c + 8];
                bfl[nt][0] = *(const uint32_t*)&tB1[n * ASTR + c];
                bfl[nt][1] = *(const uint32_t*)&tB1[n * ASTR + c + 8];
            }
            #pragma unroll
            for (int mt = 0; mt < 4; mt++)
                #pragma unroll
                for (int nt = 0; nt < 4; nt++) {
                    mma16816(acc[mt][nt], afh[mt], bfh[nt]);
                    mma16816(acc[mt][nt], afh[mt], bfl[nt]);
                    mma16816(acc[mt][nt], afl[mt], bfh[nt]);
                }
        }
        __syncthreads();
    }

    #pragma unroll
    for (int mt = 0; mt < 4; mt++) {
        int ra = row0 + wm + mt * 16 + g;
        int rb = ra + 8;
        #pragma unroll
        for (int nt = 0; nt < 4; nt++) {
            int cc = col0 + wn + nt * 8 + 2 * tig;
            float b0 = bias[cc], b1 = bias[cc + 1];
            if (ra < M)
                *(float2*)&C[(size_t)ra * N + cc] =
                    make_float2(acc[mt][nt][0] + b0, acc[mt][nt][1] + b1);
            if (rb < M)
                *(float2*)&C[(size_t)rb * N + cc] =
                    make_float2(acc[mt][nt][2] + b0, acc[mt][nt][3] + b1);
        }
    }
}
#define GEMM_SMEM (8 * GTILE * (int)sizeof(__half))   // 81920 B

// ---------------------------------------------------------------------------
// Pipelined tensor-core flash attention, split fp16.
// 256 threads (8 warps), Br=128 (16 q-rows/warp), Bc=64, D=64.
// 2-stage cp.async K/V staging shared by all 8 warps.
// ---------------------------------------------------------------------------
#define KSTR 72
#define ATILE (64 * KSTR)

__global__ __launch_bounds__(256) void attn_f16s(
    const __half* __restrict__ qh, const __half* __restrict__ ql,
    const __half* __restrict__ vth, const __half* __restrict__ vtl,
    float* __restrict__ out)
{
    extern __shared__ __half sm[];
    const int qt = blockIdx.x, h = blockIdx.y, b = blockIdx.z;
    const int tid = threadIdx.x, lane = tid & 31, wid = tid >> 5;
    const int g = lane >> 2, tig = lane & 3;
    const size_t rstr = QKVN;
    const __half* qbh = qh + (size_t)b * LL * rstr + h * DD;
    const __half* qbl = ql + (size_t)b * LL * rstr + h * DD;
    const __half* kbh = qbh + CC;
    const __half* kbl = qbl + CC;
    const __half* vbh = vth + (size_t)((b * HH + h) * DD) * VSTR;
    const __half* vbl = vtl + (size_t)((b * HH + h) * DD) * VSTR;

    // ---- Q fragments (register resident) ----
    uint32_t qfh[4][4], qfl[4][4];
    const int q0 = qt * 128 + wid * 16;
    const int qra = q0 + g, qrb = qra + 8;
    const bool va = qra < LL, vb = qrb < LL;
    #pragma unroll
    for (int kt = 0; kt < 4; kt++) {
        int c = kt * 16 + 2 * tig;
        qfh[kt][0] = va ? *(const uint32_t*)(qbh + (size_t)qra * rstr + c) : 0u;
        qfh[kt][1] = vb ? *(const uint32_t*)(qbh + (size_t)qrb * rstr + c) : 0u;
        qfh[kt][2] = va ? *(const uint32_t*)(qbh + (size_t)qra * rstr + c + 8) : 0u;
        qfh[kt][3] = vb ? *(const uint32_t*)(qbh + (size_t)qrb * rstr + c + 8) : 0u;
        qfl[kt][0] = va ? *(const uint32_t*)(qbl + (size_t)qra * rstr + c) : 0u;
        qfl[kt][1] = vb ? *(const uint32_t*)(qbl + (size_t)qrb * rstr + c) : 0u;
        qfl[kt][2] = va ? *(const uint32_t*)(qbl + (size_t)qra * rstr + c + 8) : 0u;
        qfl[kt][3] = vb ? *(const uint32_t*)(qbl + (size_t)qrb * rstr + c + 8) : 0u;
    }

    float m_a = -1e30f, m_b = -1e30f, l_a = 0.f, l_b = 0.f;
    float o[8][4];
    #pragma unroll
    for (int dt = 0; dt < 8; dt++)
        #pragma unroll
        for (int r = 0; r < 4; r++) o[dt][r] = 0.f;

    const float sc = 0.125f * 1.4426950408889634f;
    const int nkt = (LL + 63) / 64;   // 33

    // staging: 256 threads, row = tid>>2 (0..63), seg = (tid&3)*16
    auto stage = [&](int st, int kvb) {
        __half* KH = sm + st * 4 * ATILE;
        __half* KL = KH + ATILE;
        __half* VH = KL + ATILE;
        __half* VL = VH + ATILE;
        int row = tid >> 2, seg = (tid & 3) * 16;
        {
            int lkv = kvb + row;
            int sz = (lkv < LL) ? 16 : 0;
            size_t go = (size_t)(sz ? lkv : 0) * rstr + seg;
            cp16(KH + row * KSTR + seg,     kbh + go,     sz);
            cp16(KH + row * KSTR + seg + 8, kbh + go + 8, sz);
            cp16(KL + row * KSTR + seg,     kbl + go,     sz);
            cp16(KL + row * KSTR + seg + 8, kbl + go + 8, sz);
        }
        {
            #pragma unroll
            for (int c = 0; c < 2; c++) {
                int rem = LL - (kvb + seg + c * 8);
                int sz = rem >= 8 ? 16 : (rem > 0 ? rem * 2 : 0);
                size_t go = sz ? ((size_t)row * VSTR + kvb + seg + c * 8) : 0;
                cp16(VH + row * KSTR + seg + c * 8, vbh + go, sz);
                cp16(VL + row * KSTR + seg + c * 8, vbl + go, sz);
            }
        }
    };

    stage(0, 0);
    CP_COMMIT;

    for (int t = 0; t < nkt; ++t) {
        if (t + 1 < nkt) { stage((t + 1) & 1, (t + 1) * 64); CP_COMMIT; CP_WAIT1; }
        else CP_WAIT0;
        __syncthreads();

        const int st = t & 1;
        const __half* KH = sm + st * 4 * ATILE;
        const __half* KL = KH + ATILE;
        const __half* VH = KL + ATILE;
        const __half* VL = VH + ATILE;
        const int kvb = t * 64;

        // --- S = Q @ K^T ---
        float s[8][4];
        #pragma unroll
        for (int nt = 0; nt < 8; nt++)
            #pragma unroll
            for (int r = 0; r < 4; r++) s[nt][r] = 0.f;

        #pragma unroll
        for (int nt = 0; nt < 8; nt++) {
            int kr = nt * 8 + g;
            #pragma unroll
            for (int kt = 0; kt < 4; kt++) {
                int c = kt * 16 + 2 * tig;
                uint32_t bh[2], bl[2];
                bh[0] = *(const uint32_t*)&KH[kr * KSTR + c];
                bh[1] = *(const uint32_t*)&KH[kr * KSTR + c + 8];
                bl[0] = *(const uint32_t*)&KL[kr * KSTR + c];
                bl[1] = *(const uint32_t*)&KL[kr * KSTR + c + 8];
                mma16816(s[nt], qfh[kt], bh);
                mma16816(s[nt], qfh[kt], bl);
                mma16816(s[nt], qfl[kt], bh);
            }
        }
        #pragma unroll
        for (int nt = 0; nt < 8; nt++)
            #pragma unroll
            for (int r = 0; r < 4; r++) s[nt][r] *= sc;

        if (t == nkt - 1) {
            #pragma unroll
            for (int nt = 0; nt < 8; nt++) {
                int kv0 = kvb + nt * 8 + 2 * tig;
                if (kv0 >= LL)     { s[nt][0] = -1e30f; s[nt][2] = -1e30f; }
                if (kv0 + 1 >= LL) { s[nt][1] = -1e30f; s[nt][3] = -1e30f; }
            }
        }

        // --- online softmax ---
        float ma = -1e30f, mb = -1e30f;
        #pragma unroll
        for (int nt = 0; nt < 8; nt++) {
            ma = fmaxf(ma, fmaxf(s[nt][0], s[nt][1]));
            mb = fmaxf(mb, fmaxf(s[nt][2], s[nt][3]));
        }
        ma = fmaxf(ma, __shfl_xor_sync(0xffffffffu, ma, 1));
        ma = fmaxf(ma, __shfl_xor_sync(0xffffffffu, ma, 2));
        mb = fmaxf(mb, __shfl_xor_sync(0xffffffffu, mb, 1));
        mb = fmaxf(mb, __shfl_xor_sync(0xffffffffu, mb, 2));
        float mna = fmaxf(m_a, ma), mnb = fmaxf(m_b, mb);
        float ca = ex2f(m_a - mna), cb = ex2f(m_b - mnb);
        m_a = mna; m_b = mnb;

        float ra = 0.f, rb = 0.f;
        uint32_t pAh[8], pBh[8], pAl[8], pBl[8];
        #pragma unroll
        for (int nt = 0; nt < 8; nt++) {
            float p0 = ex2f(s[nt][0] - mna);
            float p1 = ex2f(s[nt][1] - mna);
            float p2 = ex2f(s[nt][2] - mnb);
            float p3 = ex2f(s[nt][3] - mnb);
            ra += p0 + p1; rb += p2 + p3;
            __half h0 = __float2half_rn(p0), h1 = __float2half_rn(p1);
            __half h2 = __float2half_rn(p2), h3 = __float2half_rn(p3);
            pAh[nt] = packh(h0, h1);
            pBh[nt] = packh(h2, h3);
            pAl[nt] = packh(__float2half_rn(p0 - __half2float(h0)),
                            __float2half_rn(p1 - __half2float(h1)));
            pBl[nt] = packh(__float2half_rn(p2 - __half2float(h2)),
                            __float2half_rn(p3 - __half2float(h3)));
        }
        ra += __shfl_xor_sync(0xffffffffu, ra, 1);
        ra += __shfl_xor_sync(0xffffffffu, ra, 2);
        rb += __shfl_xor_sync(0xffffffffu, rb, 1);
        rb += __shfl_xor_sync(0xffffffffu, rb, 2);
        l_a = l_a * ca + ra;
        l_b = l_b * cb + rb;
        #pragma unroll
        for (int dt = 0; dt < 8; dt++) {
            o[dt][0] *= ca; o[dt][1] *= ca;
            o[dt][2] *= cb; o[dt][3] *= cb;
        }

        // --- O += P @ V ---
        #pragma unroll
        for (int dt = 0; dt < 8; dt++) {
            int dr = dt * 8 + g;
            #pragma unroll
            for (int j = 0; j < 4; j++) {
                int c = j * 16 + 2 * tig;
                uint32_t bh[2], bl[2];
                bh[0] = *(const uint32_t*)&VH[dr * KSTR + c];
                bh[1] = *(const uint32_t*)&VH[dr * KSTR + c + 8];
                bl[0] = *(const uint32_t*)&VL[dr * KSTR + c];
                bl[1] = *(const uint32_t*)&VL[dr * KSTR + c + 8];
                uint32_t ah[4] = { pAh[2*j], pBh[2*j], pAh[2*j+1], pBh[2*j+1] };
                uint32_t al[4] = { pAl[2*j], pBl[2*j], pAl[2*j+1], pBl[2*j+1] };
                mma16816(o[dt], ah, bh);
                mma16816(o[dt], ah, bl);
                mma16816(o[dt], al, bh);
            }
        }
        __syncthreads();
    }

    float inva = 1.f / l_a, invb = 1.f / l_b;
    #pragma unroll
    for (int dt = 0; dt < 8; dt++) {
        int d = dt * 8 + 2 * tig;
        if (va)
            *(float2*)&out[((size_t)(b * LL + qra)) * CC + h * DD + d] =
                make_float2(o[dt][0] * inva, o[dt][1] * inva);
        if (vb)
            *(float2*)&out[((size_t)(b * LL + qrb)) * CC + h * DD + d] =
                make_float2(o[dt][2] * invb, o[dt][3] * invb);
    }
}
#define ATTN_SMEM (8 * ATILE * (int)sizeof(__half))   // 73728 B

// ---------------------------------------------------------------------------
// LayerNorm over C=1024, fused split-fp16 output. One block per row.
// ---------------------------------------------------------------------------
__global__ __launch_bounds__(256) void ln_split_kernel(
    const float* __restrict__ x, const float* __restrict__ gamma,
    const float* __restrict__ beta, __half* __restrict__ oh,
    __half* __restrict__ ol)
{
    const int row = blockIdx.x;
    const float* p = x + (size_t)row * CC;
    const int tid = threadIdx.x;

    float v[4], sum = 0.f, sq = 0.f;
    #pragma unroll
    for (int j = 0; j < 4; j++) {
        v[j] = p[tid + j * 256];
        sum += v[j];
        sq  = fmaf(v[j], v[j], sq);
    }
    #pragma unroll
    for (int ofs = 16; ofs; ofs >>= 1) {
        sum += __shfl_xor_sync(0xffffffffu, sum, ofs);
        sq  += __shfl_xor_sync(0xffffffffu, sq, ofs);
    }
    __shared__ float rs[8], rq[8];
    int wid = tid >> 5, lane = tid & 31;
    if (lane == 0) { rs[wid] = sum; rq[wid] = sq; }
    __syncthreads();
    if (tid == 0) {
        float a = 0.f, b2 = 0.f;
        #pragma unroll
        for (int i = 0; i < 8; i++) { a += rs[i]; b2 += rq[i]; }
        rs[0] = a; rq[0] = b2;
    }
    __syncthreads();
    sum = rs[0]; sq = rq[0];

    float mu   = sum * (1.f / CC);
    float var  = sq * (1.f / CC) - mu * mu;
    float rstd = rsqrtf(var + 1e-5f);
    #pragma unroll
    for (int j = 0; j < 4; j++) {
        int c = tid + j * 256;
        float y = (v[j] - mu) * rstd * gamma[c] + beta[c];
        __half h = __float2half_rn(y);
        oh[(size_t)row * CC + c] = h;
        ol[(size_t)row * CC + c] = __float2half_rn(y - __half2float(h));
    }
}

// ---------------------------------------------------------------------------
extern "C" void kernel_launch(void* const* d_in, const int* in_sizes, int n_in,
                              void* d_out, int out_size)
{
    const float* x     = (const float*)d_in[0];
    const float* rope  = (const float*)d_in[1];
    const float* Wqkv  = (const float*)d_in[2];
    const float* bqkv  = (const float*)d_in[3];
    const float* Wproj = (const float*)d_in[4];
    const float* bproj = (const float*)d_in[5];
    const float* gamma = (const float*)d_in[6];
    const float* beta  = (const float*)d_in[7];
    float* out = (float*)d_out;

    float  *qkv, *att;
    __half *xh, *xl, *qhh, *qll, *ah, *al, *wh, *wl, *ph, *pl, *vth, *vtl;
    cudaGetSymbolAddress((void**)&qkv, g_qkv);
    cudaGetSymbolAddress((void**)&att, g_att);
    cudaGetSymbolAddress((void**)&xh, g_xh);
    cudaGetSymbolAddress((void**)&xl, g_xl);
    cudaGetSymbolAddress((void**)&qhh, g_qh);
    cudaGetSymbolAddress((void**)&qll, g_ql);
    cudaGetSymbolAddress((void**)&ah, g_ah);
    cudaGetSymbolAddress((void**)&al, g_al);
    cudaGetSymbolAddress((void**)&wh, g_wh);
    cudaGetSymbolAddress((void**)&wl, g_wl);
    cudaGetSymbolAddress((void**)&ph, g_ph);
    cudaGetSymbolAddress((void**)&pl, g_pl);
    cudaGetSymbolAddress((void**)&vth, g_vth);
    cudaGetSymbolAddress((void**)&vtl, g_vtl);

    cudaFuncSetAttribute(gemm_f16s,
        cudaFuncAttributeMaxDynamicSharedMemorySize, GEMM_SMEM);
    cudaFuncSetAttribute(attn_f16s,
        cudaFuncAttributeMaxDynamicSharedMemorySize, ATTN_SMEM);

    const int nx = MROWS * CC;

    // 0. splits (x elementwise; weights transposed)
    split_kernel<<<(nx/4 + 255)/256, 256>>>(x, xh, xl, nx);
    split_trans_kernel<<<dim3(QKVN/32, CC/32), dim3(32, 8)>>>(Wqkv, wh, wl, CC, QKVN);
    split_trans_kernel<<<dim3(CC/32,  CC/32), dim3(32, 8)>>>(Wproj, ph, pl, CC, CC);

    // 1. QKV GEMM -> fp32 qkv
    {
        dim3 grid(QKVN / 128, (MROWS + 127) / 128);
        gemm_f16s<<<grid, 256, GEMM_SMEM>>>(xh, xl, wh, wl, bqkv, qkv, MROWS, QKVN, CC);
    }
    // 2. fused RoPE + split (q,k) and V transpose + split
    split_rope_qk<<<dim3(4, MROWS), 256>>>(qkv, rope, qhh, qll);
    v_trans_split<<<dim3((LL + 31)/32, 2, BB*HH), dim3(32, 8)>>>(qkv, vth, vtl);

    // 3. pipelined flash attention (Br=128, 8 warps) -> fp32 att
    {
        dim3 grid((LL + 127) / 128, HH, BB);
        attn_f16s<<<grid, 256, ATTN_SMEM>>>(qhh, qll, vth, vtl, att);
    }
    // 4. LayerNorm + split
    ln_split_kernel<<<MROWS, 256>>>(att, gamma, beta, ah, al);

    // 5. proj GEMM -> out
    {
        dim3 grid(CC / 128, (MROWS + 127) / 128);
        gemm_f16s<<<grid, 256, GEMM_SMEM>>>(ah, al, ph, pl, bproj, out, MROWS, CC, CC);
    }
}